// round 8
// baseline (speedup 1.0000x reference)
#include <cuda_runtime.h>
#include <math.h>
#include <stdint.h>

#define BB 2
#define NN 512
#define DD 64
#define HH 8
#define DHH 128

// ----------------- k_edge smem layout (floats) -----------------
#define OFF_ELOG   0        // 8*520
#define OFF_WE     4160     // 512
#define OFF_WG     4672     // 512
#define OFF_WOE    5184     // 512
#define OFF_Q      5696     // 64
#define OFF_G1     5760
#define OFF_BE1    5824
#define OFF_G2     5888
#define OFF_BE2    5952
#define OFF_CENT   6016     // 8
#define OFF_WPART  6024     // 64
#define EDGE_SMEM_FLOATS 6088
#define EDGE_SMEM_BYTES  (EDGE_SMEM_FLOATS*4)

// ----------------- mlp kernel smem layout (floats) -----------------
#define MW1_OFF  0          // sW1T [128][64] u-major (transposed W1)
#define MW2_OFF  8192       // sW2  [128][64] u-major
#define MH_OFF   16384      // sH   [128][64] (u, edge)
#define MB1_OFF  24576      // 128
#define MB2_OFF  24704      // 64
#define MLP_SMEM_FLOATS 24768
#define MLP_SMEM_BYTES  (MLP_SMEM_FLOATS*4)

#define ETILE 64

__device__ __align__(16) float g_n1[BB*NN*DD];
__device__ __align__(16) float g_q [BB*NN*DD];
__device__ __align__(16) float g_k [BB*NN*DD];
__device__ __align__(16) float g_v [BB*NN*DD];
__device__ __align__(16) float g_vc[BB*NN*DD];

// ---------------------------------------------------------------------------
// K1: node LN + Q/K/V projection.
// ---------------------------------------------------------------------------
__global__ void k_node_prep(const float* __restrict__ n,
                            const float* __restrict__ Wq,
                            const float* __restrict__ Wk,
                            const float* __restrict__ Wv,
                            const float* __restrict__ lng,
                            const float* __restrict__ lnb)
{
    int row = blockIdx.x;
    int o = threadIdx.x;
    __shared__ float sx[DD];
    __shared__ float sn1[DD];
    sx[o] = n[row*DD + o];
    __syncthreads();
    float s = 0.f;
    #pragma unroll
    for (int k = 0; k < DD; k++) s += sx[k];
    float m = s * (1.f/DD);
    float v = 0.f;
    #pragma unroll
    for (int k = 0; k < DD; k++) { float d = sx[k]-m; v += d*d; }
    v *= (1.f/DD);
    float rstd = rsqrtf(v + 1e-5f);
    float n1 = (sx[o]-m)*rstd*lng[o] + lnb[o];
    sn1[o] = n1;
    g_n1[row*DD + o] = n1;
    __syncthreads();
    float q = 0.f, kk = 0.f, vv = 0.f;
    #pragma unroll
    for (int k = 0; k < DD; k++) {
        float a = sn1[k];
        q  += a * Wq[k*DD + o];
        kk += a * Wk[k*DD + o];
        vv += a * Wv[k*DD + o];
    }
    g_q[row*DD + o] = q;
    g_k[row*DD + o] = kk;
    g_v[row*DD + o] = vv;
}

// ---------------------------------------------------------------------------
// K2: edge attention. Writes e3 (pre-MLP value) into e_out.
// NOTE: explicit minBlocks=1 so ptxas uses full register budget (no spill).
// ---------------------------------------------------------------------------
__global__ void __launch_bounds__(256, 1)
k_edge(const float* __restrict__ e,
       const float* __restrict__ We, const float* __restrict__ Wg,
       const float* __restrict__ WoE,
       const float* __restrict__ lg1, const float* __restrict__ lb1,
       const float* __restrict__ lg2, const float* __restrict__ lb2,
       float* __restrict__ e_out)
{
    extern __shared__ float sm[];
    float* sElog  = sm + OFF_ELOG;
    float* sWe    = sm + OFF_WE;
    float* sWg    = sm + OFF_WG;
    float* sWoE   = sm + OFF_WOE;
    float* sQ     = sm + OFF_Q;
    float* sG1    = sm + OFF_G1;
    float* sBe1   = sm + OFF_BE1;
    float* sG2    = sm + OFF_G2;
    float* sBe2   = sm + OFF_BE2;
    float* sCent  = sm + OFF_CENT;
    float* sWpart = sm + OFF_WPART;

    const int i   = blockIdx.x;
    const int b   = blockIdx.y;
    const int tid = threadIdx.x;
    const int lane = tid & 31;
    const int warp = tid >> 5;
    const int rowbn = b*NN + i;

    for (int t = tid; t < 512; t += 256) {
        sWe[t] = We[t]; sWg[t] = Wg[t]; sWoE[t] = WoE[t];
    }
    if (tid < 64) {
        sQ[tid]   = g_q[rowbn*DD + tid];
        sG1[tid]  = lg1[tid]; sBe1[tid] = lb1[tid];
        sG2[tid]  = lg2[tid]; sBe2[tid] = lb2[tid];
    }
    __syncthreads();

    const float* erow = e + (size_t)rowbn * NN * DD;
    const float scale = 0.35355339059327373f;

    float gacc[HH];
    #pragma unroll
    for (int h = 0; h < HH; h++) gacc[h] = 0.f;

    #pragma unroll
    for (int jj = 0; jj < 2; jj++) {
        const int j = tid + jj*256;
        float4 x4[16];
        const float4* xp = (const float4*)(erow + j*DD);
        #pragma unroll
        for (int q = 0; q < 16; q++) x4[q] = xp[q];

        float s0=0,s1=0,s2=0,s3=0;
        #pragma unroll
        for (int q = 0; q < 16; q++) { s0+=x4[q].x; s1+=x4[q].y; s2+=x4[q].z; s3+=x4[q].w; }
        float m = ((s0+s1)+(s2+s3)) * (1.f/64.f);
        float v0=0,v1=0,v2=0,v3=0;
        #pragma unroll
        for (int q = 0; q < 16; q++) {
            float dx=x4[q].x-m, dy=x4[q].y-m, dz=x4[q].z-m, dw=x4[q].w-m;
            v0+=dx*dx; v1+=dy*dy; v2+=dz*dz; v3+=dw*dw;
        }
        float rstd = rsqrtf(((v0+v1)+(v2+v3))*(1.f/64.f) + 1e-5f);

        float Eh[HH], Gh[HH];
        #pragma unroll
        for (int h = 0; h < HH; h++) { Eh[h]=0.f; Gh[h]=0.f; }
        #pragma unroll
        for (int q = 0; q < 16; q++) {
            float xs[4] = {x4[q].x, x4[q].y, x4[q].z, x4[q].w};
            #pragma unroll
            for (int c = 0; c < 4; c++) {
                int k = q*4 + c;
                float e1 = (xs[c]-m)*rstd*sG1[k] + sBe1[k];
                const float4* we = (const float4*)(sWe + k*8);
                const float4* wg = (const float4*)(sWg + k*8);
                float4 a0 = we[0], a1 = we[1];
                float4 c0 = wg[0], c1 = wg[1];
                Eh[0]+=e1*a0.x; Eh[1]+=e1*a0.y; Eh[2]+=e1*a0.z; Eh[3]+=e1*a0.w;
                Eh[4]+=e1*a1.x; Eh[5]+=e1*a1.y; Eh[6]+=e1*a1.z; Eh[7]+=e1*a1.w;
                Gh[0]+=e1*c0.x; Gh[1]+=e1*c0.y; Gh[2]+=e1*c0.z; Gh[3]+=e1*c0.w;
                Gh[4]+=e1*c1.x; Gh[5]+=e1*c1.y; Gh[6]+=e1*c1.z; Gh[7]+=e1*c1.w;
            }
        }

        float ac[HH];
        #pragma unroll
        for (int h = 0; h < HH; h++) ac[h] = 0.f;
        const float4* kp = (const float4*)(g_k + (b*NN + j)*DD);
        const float4* qp = (const float4*)sQ;
        #pragma unroll
        for (int q = 0; q < 16; q++) {
            float4 kv = kp[q], qv = qp[q];
            ac[q>>1] += qv.x*kv.x + qv.y*kv.y + qv.z*kv.z + qv.w*kv.w;
        }

        #pragma unroll
        for (int h = 0; h < HH; h++) {
            float a = fminf(fmaxf(ac[h]*scale, -5.f), 5.f);
            sElog[h*520 + j] = a + Eh[h];
            gacc[h] += 1.f/(1.f + expf(-Gh[h]));
        }
    }

    #pragma unroll
    for (int h = 0; h < HH; h++) {
        #pragma unroll
        for (int off = 16; off > 0; off >>= 1)
            gacc[h] += __shfl_xor_sync(0xffffffffu, gacc[h], off);
    }
    if (lane == 0) {
        #pragma unroll
        for (int h = 0; h < HH; h++) sWpart[warp*8 + h] = gacc[h];
    }
    __syncthreads();
    if (tid < 8) {
        float s = 0.f;
        #pragma unroll
        for (int w = 0; w < 8; w++) s += sWpart[w*8 + tid];
        sCent[tid] = log1pf(s);
    }
    __syncthreads();

    {
        const int h = warp;
        const float* el = sElog + h*520;
        float mmax = -1e30f;
        for (int j = lane; j < NN; j += 32) mmax = fmaxf(mmax, el[j]);
        #pragma unroll
        for (int off = 16; off > 0; off >>= 1)
            mmax = fmaxf(mmax, __shfl_xor_sync(0xffffffffu, mmax, off));

        float denom = 0.f;
        float p0=0,p1=0,p2=0,p3=0,p4=0,p5=0,p6=0,p7=0;
        for (int j = lane; j < NN; j += 32) {
            float t = expf(el[j] - mmax);
            denom += t;
            const float4* vp = (const float4*)(g_v + (b*NN + j)*DD + h*8);
            float4 va = vp[0], vb = vp[1];
            p0 += t*va.x; p1 += t*va.y; p2 += t*va.z; p3 += t*va.w;
            p4 += t*vb.x; p5 += t*vb.y; p6 += t*vb.z; p7 += t*vb.w;
        }
        #pragma unroll
        for (int off = 16; off > 0; off >>= 1) {
            denom += __shfl_xor_sync(0xffffffffu, denom, off);
            p0 += __shfl_xor_sync(0xffffffffu, p0, off);
            p1 += __shfl_xor_sync(0xffffffffu, p1, off);
            p2 += __shfl_xor_sync(0xffffffffu, p2, off);
            p3 += __shfl_xor_sync(0xffffffffu, p3, off);
            p4 += __shfl_xor_sync(0xffffffffu, p4, off);
            p5 += __shfl_xor_sync(0xffffffffu, p5, off);
            p6 += __shfl_xor_sync(0xffffffffu, p6, off);
            p7 += __shfl_xor_sync(0xffffffffu, p7, off);
        }
        if (lane == 0) {
            float c = sCent[h] / denom;
            float* dst = g_vc + rowbn*DD + h*8;
            dst[0]=p0*c; dst[1]=p1*c; dst[2]=p2*c; dst[3]=p3*c;
            dst[4]=p4*c; dst[5]=p5*c; dst[6]=p6*c; dst[7]=p7*c;
        }
    }

    // pass 2: e3 = LN2( LN1(e) + Elog @ Wo_e ) -> e_out
    #pragma unroll
    for (int jj = 0; jj < 2; jj++) {
        const int j = tid + jj*256;
        float xv[64];
        const float4* xp = (const float4*)(erow + j*DD);
        #pragma unroll
        for (int q = 0; q < 16; q++) {
            float4 t = xp[q];
            xv[q*4+0]=t.x; xv[q*4+1]=t.y; xv[q*4+2]=t.z; xv[q*4+3]=t.w;
        }
        float s0=0,s1=0,s2=0,s3=0;
        #pragma unroll
        for (int k = 0; k < 64; k += 4) { s0+=xv[k]; s1+=xv[k+1]; s2+=xv[k+2]; s3+=xv[k+3]; }
        float m = ((s0+s1)+(s2+s3))*(1.f/64.f);
        float v0=0,v1=0,v2=0,v3=0;
        #pragma unroll
        for (int k = 0; k < 64; k += 4) {
            float d0=xv[k]-m, d1=xv[k+1]-m, d2=xv[k+2]-m, d3=xv[k+3]-m;
            v0+=d0*d0; v1+=d1*d1; v2+=d2*d2; v3+=d3*d3;
        }
        float rstd = rsqrtf(((v0+v1)+(v2+v3))*(1.f/64.f) + 1e-5f);

        float el[HH];
        #pragma unroll
        for (int h = 0; h < HH; h++) el[h] = sElog[h*520 + j];

        #pragma unroll
        for (int k = 0; k < 64; k++) {
            float a = (xv[k]-m)*rstd*sG1[k] + sBe1[k];
            #pragma unroll
            for (int h = 0; h < HH; h++) a += el[h]*sWoE[h*64 + k];
            xv[k] = a;
        }
        s0=s1=s2=s3=0;
        #pragma unroll
        for (int k = 0; k < 64; k += 4) { s0+=xv[k]; s1+=xv[k+1]; s2+=xv[k+2]; s3+=xv[k+3]; }
        float m2 = ((s0+s1)+(s2+s3))*(1.f/64.f);
        v0=v1=v2=v3=0;
        #pragma unroll
        for (int k = 0; k < 64; k += 4) {
            float d0=xv[k]-m2, d1=xv[k+1]-m2, d2=xv[k+2]-m2, d3=xv[k+3]-m2;
            v0+=d0*d0; v1+=d1*d1; v2+=d2*d2; v3+=d3*d3;
        }
        float rstd2 = rsqrtf(((v0+v1)+(v2+v3))*(1.f/64.f) + 1e-5f);

        float4* op = (float4*)(e_out + ((size_t)rowbn*NN + j)*DD);
        #pragma unroll
        for (int q = 0; q < 16; q++) {
            float4 r;
            r.x = (xv[q*4+0]-m2)*rstd2*sG2[q*4+0] + sBe2[q*4+0];
            r.y = (xv[q*4+1]-m2)*rstd2*sG2[q*4+1] + sBe2[q*4+1];
            r.z = (xv[q*4+2]-m2)*rstd2*sG2[q*4+2] + sBe2[q*4+2];
            r.w = (xv[q*4+3]-m2)*rstd2*sG2[q*4+3] + sBe2[q*4+3];
            op[q] = r;
        }
    }
}

// ---------------------------------------------------------------------------
// K3: edge MLP, pure FFMA, zero dynamic array indexing, minBlocks=1 (no cap).
// In-place on e_out: e3 -> e3 + relu(mlp(e3)).
// grid = 8192 CTAs, 256 threads, tile = 64 edges, 4 threads per edge.
// ---------------------------------------------------------------------------
__global__ void __launch_bounds__(256, 1)
k_edge_mlp(float* __restrict__ eio,
           const float* __restrict__ W1, const float* __restrict__ b1,
           const float* __restrict__ W2, const float* __restrict__ b2)
{
    extern __shared__ float sm[];
    float* sW1T = sm + MW1_OFF;   // [u][k] 128x64
    float* sW2  = sm + MW2_OFF;   // [u][k] 128x64
    float* sH   = sm + MH_OFF;    // [u][edge] 128x64
    float* sB1  = sm + MB1_OFF;
    float* sB2  = sm + MB2_OFF;

    const int tid  = threadIdx.x;
    const int edge = tid & 63;       // 0..63
    const int part = tid >> 6;       // 0..3
    const size_t base = (size_t)blockIdx.x * ETILE;

    // weights: W1 is [k][u] in gmem -> transpose to [u][k]; W2 already [u][k]
    for (int t = tid; t < 64*DHH; t += 256) {
        int k = t >> 7, u = t & 127;
        sW1T[u*64 + k] = W1[t];
    }
    for (int t = tid; t < DHH*64; t += 256) {
        sW2[t] = W2[t];
    }
    if (tid < 128) sB1[tid] = b1[tid];
    if (tid < 64)  sB2[tid] = b2[tid];
    __syncthreads();

    // load this thread's edge x into registers (constant-indexed only)
    float x[64];
    {
        const float4* xp = (const float4*)(eio + (base + edge)*64);
        #pragma unroll
        for (int q = 0; q < 16; q++) {
            float4 t = xp[q];
            x[q*4+0]=t.x; x[q*4+1]=t.y; x[q*4+2]=t.z; x[q*4+3]=t.w;
        }
    }

    // ---------------- phase 1: hidden (32 units per thread) ----------------
    const int u0 = part*32;
    #pragma unroll 4
    for (int uu = 0; uu < 32; uu++) {
        int u = u0 + uu;
        const float4* w = (const float4*)(sW1T + u*64);   // warp-broadcast reads
        float a0=0,a1=0,a2=0,a3=0;
        #pragma unroll
        for (int q = 0; q < 16; q++) {
            float4 wv = w[q];
            a0 += x[q*4+0]*wv.x;
            a1 += x[q*4+1]*wv.y;
            a2 += x[q*4+2]*wv.z;
            a3 += x[q*4+3]*wv.w;
        }
        sH[u*64 + edge] = fmaxf(sB1[u] + ((a0+a1)+(a2+a3)), 0.f);
    }
    __syncthreads();

    // ---------------- phase 2: output (16 channels per thread) -------------
    const int k0 = part*16;
    float acc[16];
    #pragma unroll
    for (int t = 0; t < 16; t++) acc[t] = sB2[k0 + t];

    #pragma unroll 4
    for (int u = 0; u < DHH; u++) {
        float hv = sH[u*64 + edge];
        const float4* w = (const float4*)(sW2 + u*64 + k0);
        float4 w0 = w[0], w1v = w[1], w2v = w[2], w3v = w[3];
        acc[0]  += hv*w0.x;  acc[1]  += hv*w0.y;  acc[2]  += hv*w0.z;  acc[3]  += hv*w0.w;
        acc[4]  += hv*w1v.x; acc[5]  += hv*w1v.y; acc[6]  += hv*w1v.z; acc[7]  += hv*w1v.w;
        acc[8]  += hv*w2v.x; acc[9]  += hv*w2v.y; acc[10] += hv*w2v.z; acc[11] += hv*w2v.w;
        acc[12] += hv*w3v.x; acc[13] += hv*w3v.y; acc[14] += hv*w3v.z; acc[15] += hv*w3v.w;
    }

    // residual re-read from gmem (runtime ADDRESS, no dynamic array index)
    const float4* rp = (const float4*)(eio + (base + edge)*64 + k0);
    float4* op = (float4*)(eio + (base + edge)*64 + k0);
    #pragma unroll
    for (int q = 0; q < 4; q++) {
        float4 res = rp[q];
        float4 r;
        r.x = res.x + fmaxf(acc[q*4+0], 0.f);
        r.y = res.y + fmaxf(acc[q*4+1], 0.f);
        r.z = res.z + fmaxf(acc[q*4+2], 0.f);
        r.w = res.w + fmaxf(acc[q*4+3], 0.f);
        op[q] = r;
    }
}

// ---------------------------------------------------------------------------
// K4: node finish.
// ---------------------------------------------------------------------------
__global__ void k_node_finish(const float* __restrict__ Wo_n,
                              const float* __restrict__ lng,
                              const float* __restrict__ lnb,
                              const float* __restrict__ W1,
                              const float* __restrict__ Bi1,
                              const float* __restrict__ W2,
                              const float* __restrict__ Bi2,
                              float* __restrict__ n_out)
{
    int row = blockIdx.x;
    int o = threadIdx.x;
    __shared__ float svc[DD];
    __shared__ float sn2[DD];
    __shared__ float sn3[DD];
    __shared__ float sh[DHH];
    svc[o] = g_vc[row*DD + o];
    __syncthreads();
    float acc = 0.f;
    #pragma unroll
    for (int k = 0; k < DD; k++) acc += svc[k]*Wo_n[k*DD + o];
    float n2 = g_n1[row*DD + o] + acc;
    sn2[o] = n2;
    __syncthreads();
    float s = 0.f;
    #pragma unroll
    for (int k = 0; k < DD; k++) s += sn2[k];
    float m = s*(1.f/DD);
    float v = 0.f;
    #pragma unroll
    for (int k = 0; k < DD; k++) { float d = sn2[k]-m; v += d*d; }
    v *= (1.f/DD);
    float rstd = rsqrtf(v + 1e-5f);
    float n3 = (n2-m)*rstd*lng[o] + lnb[o];
    sn3[o] = n3;
    __syncthreads();
    #pragma unroll
    for (int uu = 0; uu < 2; uu++) {
        int u = o + uu*64;
        float h = Bi1[u];
        #pragma unroll
        for (int k = 0; k < DD; k++) h += sn3[k]*W1[k*DHH + u];
        sh[u] = fmaxf(h, 0.f);
    }
    __syncthreads();
    float oacc = Bi2[o];
    #pragma unroll
    for (int u = 0; u < DHH; u++) oacc += sh[u]*W2[u*DD + o];
    n_out[row*DD + o] = n3 + fmaxf(oacc, 0.f);
}

extern "C" void kernel_launch(void* const* d_in, const int* in_sizes, int n_in,
                              void* d_out, int out_size)
{
    const float* n       = (const float*)d_in[0];
    const float* e       = (const float*)d_in[1];
    const float* Wq      = (const float*)d_in[2];
    const float* Wk      = (const float*)d_in[3];
    const float* Wv      = (const float*)d_in[4];
    const float* Wo_n    = (const float*)d_in[5];
    const float* We      = (const float*)d_in[6];
    const float* Wg      = (const float*)d_in[7];
    const float* Wo_e    = (const float*)d_in[8];
    const float* ln_n1_g = (const float*)d_in[9];
    const float* ln_n1_b = (const float*)d_in[10];
    const float* ln_e1_g = (const float*)d_in[11];
    const float* ln_e1_b = (const float*)d_in[12];
    const float* ln_n2_g = (const float*)d_in[13];
    const float* ln_n2_b = (const float*)d_in[14];
    const float* ln_e2_g = (const float*)d_in[15];
    const float* ln_e2_b = (const float*)d_in[16];
    const float* mn_w1   = (const float*)d_in[17];
    const float* mn_b1   = (const float*)d_in[18];
    const float* mn_w2   = (const float*)d_in[19];
    const float* mn_b2   = (const float*)d_in[20];
    const float* me_w1   = (const float*)d_in[21];
    const float* me_b1   = (const float*)d_in[22];
    const float* me_w2   = (const float*)d_in[23];
    const float* me_b2   = (const float*)d_in[24];

    float* out   = (float*)d_out;
    float* n_out = out;
    float* e_out = out + BB*NN*DD;

    cudaFuncSetAttribute(k_edge, cudaFuncAttributeMaxDynamicSharedMemorySize, EDGE_SMEM_BYTES);
    cudaFuncSetAttribute(k_edge_mlp, cudaFuncAttributeMaxDynamicSharedMemorySize, MLP_SMEM_BYTES);

    k_node_prep<<<BB*NN, 64>>>(n, Wq, Wk, Wv, ln_n1_g, ln_n1_b);

    dim3 grid(NN, BB);
    k_edge<<<grid, 256, EDGE_SMEM_BYTES>>>(e, We, Wg, Wo_e,
                                           ln_e1_g, ln_e1_b, ln_e2_g, ln_e2_b,
                                           e_out);

    k_edge_mlp<<<(BB*NN*NN)/ETILE, 256, MLP_SMEM_BYTES>>>(e_out, me_w1, me_b1, me_w2, me_b2);

    k_node_finish<<<BB*NN, 64>>>(Wo_n, ln_n2_g, ln_n2_b,
                                 mn_w1, mn_b1, mn_w2, mn_b2, n_out);
}

// round 9
// speedup vs baseline: 1.4672x; 1.4672x over previous
#include <cuda_runtime.h>
#include <math.h>
#include <stdint.h>

#define BB 2
#define NN 512
#define DD 64
#define HH 8
#define DHH 128

// ----------------- k_edge smem layout (floats) -----------------
#define OFF_ELOG   0        // 8*520
#define OFF_WE     4160     // 512
#define OFF_WG     4672     // 512
#define OFF_WOE    5184     // 512
#define OFF_Q      5696     // 64
#define OFF_G1     5760
#define OFF_BE1    5824
#define OFF_G2     5888
#define OFF_BE2    5952
#define OFF_CENT   6016     // 8
#define OFF_WPART  6024     // 64
#define EDGE_SMEM_FLOATS 6088
#define EDGE_SMEM_BYTES  (EDGE_SMEM_FLOATS*4)

// ----------------- mma mlp kernel smem layout (floats) -----------------
#define SA_OFF   0          // 128 x 68 fp32  (8704)
#define SW1_OFF  8704       // 64 x 136 tf32  (8704)
#define SH_OFF   17408      // 128 x 132 tf32 (16896)
#define SW2_OFF  34304      // 128 x 72 tf32  (9216)
#define SB1_OFF  43520      // 128
#define SB2_OFF  43648      // 64
#define MLP_SMEM_FLOATS 43712
#define MLP_SMEM_BYTES  (MLP_SMEM_FLOATS*4)   // 174848 B

__device__ __align__(16) float g_n1[BB*NN*DD];
__device__ __align__(16) float g_q [BB*NN*DD];
__device__ __align__(16) float g_k [BB*NN*DD];
__device__ __align__(16) float g_v [BB*NN*DD];
__device__ __align__(16) float g_vc[BB*NN*DD];

__device__ __forceinline__ uint32_t f2tf32(float x) {
    uint32_t r;
    asm("cvt.rna.tf32.f32 %0, %1;" : "=r"(r) : "f"(x));
    return r;
}

// scalar-reference accumulators: no array decay, register-resident
__device__ __forceinline__ void mma_tf32(float& c0, float& c1, float& c2, float& c3,
                                         uint32_t a0, uint32_t a1,
                                         uint32_t a2, uint32_t a3,
                                         uint32_t b0, uint32_t b1) {
    asm volatile(
        "mma.sync.aligned.m16n8k8.row.col.f32.tf32.tf32.f32 "
        "{%0,%1,%2,%3},{%4,%5,%6,%7},{%8,%9},{%0,%1,%2,%3};"
        : "+f"(c0), "+f"(c1), "+f"(c2), "+f"(c3)
        : "r"(a0), "r"(a1), "r"(a2), "r"(a3), "r"(b0), "r"(b1));
}

// ---------------------------------------------------------------------------
// K1: node LN + Q/K/V projection.
// ---------------------------------------------------------------------------
__global__ void k_node_prep(const float* __restrict__ n,
                            const float* __restrict__ Wq,
                            const float* __restrict__ Wk,
                            const float* __restrict__ Wv,
                            const float* __restrict__ lng,
                            const float* __restrict__ lnb)
{
    int row = blockIdx.x;
    int o = threadIdx.x;
    __shared__ float sx[DD];
    __shared__ float sn1[DD];
    sx[o] = n[row*DD + o];
    __syncthreads();
    float s = 0.f;
    #pragma unroll
    for (int k = 0; k < DD; k++) s += sx[k];
    float m = s * (1.f/DD);
    float v = 0.f;
    #pragma unroll
    for (int k = 0; k < DD; k++) { float d = sx[k]-m; v += d*d; }
    v *= (1.f/DD);
    float rstd = rsqrtf(v + 1e-5f);
    float n1 = (sx[o]-m)*rstd*lng[o] + lnb[o];
    sn1[o] = n1;
    g_n1[row*DD + o] = n1;
    __syncthreads();
    float q = 0.f, kk = 0.f, vv = 0.f;
    #pragma unroll
    for (int k = 0; k < DD; k++) {
        float a = sn1[k];
        q  += a * Wq[k*DD + o];
        kk += a * Wk[k*DD + o];
        vv += a * Wv[k*DD + o];
    }
    g_q[row*DD + o] = q;
    g_k[row*DD + o] = kk;
    g_v[row*DD + o] = vv;
}

// ---------------------------------------------------------------------------
// K2: edge attention. Writes e3 (pre-MLP value) into e_out. (unchanged, R8)
// ---------------------------------------------------------------------------
__global__ void __launch_bounds__(256, 1)
k_edge(const float* __restrict__ e,
       const float* __restrict__ We, const float* __restrict__ Wg,
       const float* __restrict__ WoE,
       const float* __restrict__ lg1, const float* __restrict__ lb1,
       const float* __restrict__ lg2, const float* __restrict__ lb2,
       float* __restrict__ e_out)
{
    extern __shared__ float sm[];
    float* sElog  = sm + OFF_ELOG;
    float* sWe    = sm + OFF_WE;
    float* sWg    = sm + OFF_WG;
    float* sWoE   = sm + OFF_WOE;
    float* sQ     = sm + OFF_Q;
    float* sG1    = sm + OFF_G1;
    float* sBe1   = sm + OFF_BE1;
    float* sG2    = sm + OFF_G2;
    float* sBe2   = sm + OFF_BE2;
    float* sCent  = sm + OFF_CENT;
    float* sWpart = sm + OFF_WPART;

    const int i   = blockIdx.x;
    const int b   = blockIdx.y;
    const int tid = threadIdx.x;
    const int lane = tid & 31;
    const int warp = tid >> 5;
    const int rowbn = b*NN + i;

    for (int t = tid; t < 512; t += 256) {
        sWe[t] = We[t]; sWg[t] = Wg[t]; sWoE[t] = WoE[t];
    }
    if (tid < 64) {
        sQ[tid]   = g_q[rowbn*DD + tid];
        sG1[tid]  = lg1[tid]; sBe1[tid] = lb1[tid];
        sG2[tid]  = lg2[tid]; sBe2[tid] = lb2[tid];
    }
    __syncthreads();

    const float* erow = e + (size_t)rowbn * NN * DD;
    const float scale = 0.35355339059327373f;

    float gacc[HH];
    #pragma unroll
    for (int h = 0; h < HH; h++) gacc[h] = 0.f;

    #pragma unroll
    for (int jj = 0; jj < 2; jj++) {
        const int j = tid + jj*256;
        float4 x4[16];
        const float4* xp = (const float4*)(erow + j*DD);
        #pragma unroll
        for (int q = 0; q < 16; q++) x4[q] = xp[q];

        float s0=0,s1=0,s2=0,s3=0;
        #pragma unroll
        for (int q = 0; q < 16; q++) { s0+=x4[q].x; s1+=x4[q].y; s2+=x4[q].z; s3+=x4[q].w; }
        float m = ((s0+s1)+(s2+s3)) * (1.f/64.f);
        float v0=0,v1=0,v2=0,v3=0;
        #pragma unroll
        for (int q = 0; q < 16; q++) {
            float dx=x4[q].x-m, dy=x4[q].y-m, dz=x4[q].z-m, dw=x4[q].w-m;
            v0+=dx*dx; v1+=dy*dy; v2+=dz*dz; v3+=dw*dw;
        }
        float rstd = rsqrtf(((v0+v1)+(v2+v3))*(1.f/64.f) + 1e-5f);

        float Eh[HH], Gh[HH];
        #pragma unroll
        for (int h = 0; h < HH; h++) { Eh[h]=0.f; Gh[h]=0.f; }
        #pragma unroll
        for (int q = 0; q < 16; q++) {
            float xs[4] = {x4[q].x, x4[q].y, x4[q].z, x4[q].w};
            #pragma unroll
            for (int c = 0; c < 4; c++) {
                int k = q*4 + c;
                float e1 = (xs[c]-m)*rstd*sG1[k] + sBe1[k];
                const float4* we = (const float4*)(sWe + k*8);
                const float4* wg = (const float4*)(sWg + k*8);
                float4 a0 = we[0], a1 = we[1];
                float4 c0 = wg[0], c1 = wg[1];
                Eh[0]+=e1*a0.x; Eh[1]+=e1*a0.y; Eh[2]+=e1*a0.z; Eh[3]+=e1*a0.w;
                Eh[4]+=e1*a1.x; Eh[5]+=e1*a1.y; Eh[6]+=e1*a1.z; Eh[7]+=e1*a1.w;
                Gh[0]+=e1*c0.x; Gh[1]+=e1*c0.y; Gh[2]+=e1*c0.z; Gh[3]+=e1*c0.w;
                Gh[4]+=e1*c1.x; Gh[5]+=e1*c1.y; Gh[6]+=e1*c1.z; Gh[7]+=e1*c1.w;
            }
        }

        float ac[HH];
        #pragma unroll
        for (int h = 0; h < HH; h++) ac[h] = 0.f;
        const float4* kp = (const float4*)(g_k + (b*NN + j)*DD);
        const float4* qp = (const float4*)sQ;
        #pragma unroll
        for (int q = 0; q < 16; q++) {
            float4 kv = kp[q], qv = qp[q];
            ac[q>>1] += qv.x*kv.x + qv.y*kv.y + qv.z*kv.z + qv.w*kv.w;
        }

        #pragma unroll
        for (int h = 0; h < HH; h++) {
            float a = fminf(fmaxf(ac[h]*scale, -5.f), 5.f);
            sElog[h*520 + j] = a + Eh[h];
            gacc[h] += 1.f/(1.f + expf(-Gh[h]));
        }
    }

    #pragma unroll
    for (int h = 0; h < HH; h++) {
        #pragma unroll
        for (int off = 16; off > 0; off >>= 1)
            gacc[h] += __shfl_xor_sync(0xffffffffu, gacc[h], off);
    }
    if (lane == 0) {
        #pragma unroll
        for (int h = 0; h < HH; h++) sWpart[warp*8 + h] = gacc[h];
    }
    __syncthreads();
    if (tid < 8) {
        float s = 0.f;
        #pragma unroll
        for (int w = 0; w < 8; w++) s += sWpart[w*8 + tid];
        sCent[tid] = log1pf(s);
    }
    __syncthreads();

    {
        const int h = warp;
        const float* el = sElog + h*520;
        float mmax = -1e30f;
        for (int j = lane; j < NN; j += 32) mmax = fmaxf(mmax, el[j]);
        #pragma unroll
        for (int off = 16; off > 0; off >>= 1)
            mmax = fmaxf(mmax, __shfl_xor_sync(0xffffffffu, mmax, off));

        float denom = 0.f;
        float p0=0,p1=0,p2=0,p3=0,p4=0,p5=0,p6=0,p7=0;
        for (int j = lane; j < NN; j += 32) {
            float t = expf(el[j] - mmax);
            denom += t;
            const float4* vp = (const float4*)(g_v + (b*NN + j)*DD + h*8);
            float4 va = vp[0], vb = vp[1];
            p0 += t*va.x; p1 += t*va.y; p2 += t*va.z; p3 += t*va.w;
            p4 += t*vb.x; p5 += t*vb.y; p6 += t*vb.z; p7 += t*vb.w;
        }
        #pragma unroll
        for (int off = 16; off > 0; off >>= 1) {
            denom += __shfl_xor_sync(0xffffffffu, denom, off);
            p0 += __shfl_xor_sync(0xffffffffu, p0, off);
            p1 += __shfl_xor_sync(0xffffffffu, p1, off);
            p2 += __shfl_xor_sync(0xffffffffu, p2, off);
            p3 += __shfl_xor_sync(0xffffffffu, p3, off);
            p4 += __shfl_xor_sync(0xffffffffu, p4, off);
            p5 += __shfl_xor_sync(0xffffffffu, p5, off);
            p6 += __shfl_xor_sync(0xffffffffu, p6, off);
            p7 += __shfl_xor_sync(0xffffffffu, p7, off);
        }
        if (lane == 0) {
            float c = sCent[h] / denom;
            float* dst = g_vc + rowbn*DD + h*8;
            dst[0]=p0*c; dst[1]=p1*c; dst[2]=p2*c; dst[3]=p3*c;
            dst[4]=p4*c; dst[5]=p5*c; dst[6]=p6*c; dst[7]=p7*c;
        }
    }

    // pass 2: e3 = LN2( LN1(e) + Elog @ Wo_e ) -> e_out
    #pragma unroll
    for (int jj = 0; jj < 2; jj++) {
        const int j = tid + jj*256;
        float xv[64];
        const float4* xp = (const float4*)(erow + j*DD);
        #pragma unroll
        for (int q = 0; q < 16; q++) {
            float4 t = xp[q];
            xv[q*4+0]=t.x; xv[q*4+1]=t.y; xv[q*4+2]=t.z; xv[q*4+3]=t.w;
        }
        float s0=0,s1=0,s2=0,s3=0;
        #pragma unroll
        for (int k = 0; k < 64; k += 4) { s0+=xv[k]; s1+=xv[k+1]; s2+=xv[k+2]; s3+=xv[k+3]; }
        float m = ((s0+s1)+(s2+s3))*(1.f/64.f);
        float v0=0,v1=0,v2=0,v3=0;
        #pragma unroll
        for (int k = 0; k < 64; k += 4) {
            float d0=xv[k]-m, d1=xv[k+1]-m, d2=xv[k+2]-m, d3=xv[k+3]-m;
            v0+=d0*d0; v1+=d1*d1; v2+=d2*d2; v3+=d3*d3;
        }
        float rstd = rsqrtf(((v0+v1)+(v2+v3))*(1.f/64.f) + 1e-5f);

        float el[HH];
        #pragma unroll
        for (int h = 0; h < HH; h++) el[h] = sElog[h*520 + j];

        #pragma unroll
        for (int k = 0; k < 64; k++) {
            float a = (xv[k]-m)*rstd*sG1[k] + sBe1[k];
            #pragma unroll
            for (int h = 0; h < HH; h++) a += el[h]*sWoE[h*64 + k];
            xv[k] = a;
        }
        s0=s1=s2=s3=0;
        #pragma unroll
        for (int k = 0; k < 64; k += 4) { s0+=xv[k]; s1+=xv[k+1]; s2+=xv[k+2]; s3+=xv[k+3]; }
        float m2 = ((s0+s1)+(s2+s3))*(1.f/64.f);
        v0=v1=v2=v3=0;
        #pragma unroll
        for (int k = 0; k < 64; k += 4) {
            float d0=xv[k]-m2, d1=xv[k+1]-m2, d2=xv[k+2]-m2, d3=xv[k+3]-m2;
            v0+=d0*d0; v1+=d1*d1; v2+=d2*d2; v3+=d3*d3;
        }
        float rstd2 = rsqrtf(((v0+v1)+(v2+v3))*(1.f/64.f) + 1e-5f);

        float4* op = (float4*)(e_out + ((size_t)rowbn*NN + j)*DD);
        #pragma unroll
        for (int q = 0; q < 16; q++) {
            float4 r;
            r.x = (xv[q*4+0]-m2)*rstd2*sG2[q*4+0] + sBe2[q*4+0];
            r.y = (xv[q*4+1]-m2)*rstd2*sG2[q*4+1] + sBe2[q*4+1];
            r.z = (xv[q*4+2]-m2)*rstd2*sG2[q*4+2] + sBe2[q*4+2];
            r.w = (xv[q*4+3]-m2)*rstd2*sG2[q*4+3] + sBe2[q*4+3];
            op[q] = r;
        }
    }
}

// ---------------------------------------------------------------------------
// K3: edge MLP via tf32 mma.sync. In-place on e_out: e3 -> e3 + relu(mlp(e3)).
// grid = 4096 CTAs, 256 threads (8 warps), tile = 128 edges, warp = 16 rows.
// All local arrays constant-indexed; accumulators scalar; minBlocks=1.
// ---------------------------------------------------------------------------
__global__ void __launch_bounds__(256, 1)
k_edge_mlp(float* __restrict__ eio,
           const float* __restrict__ W1, const float* __restrict__ b1,
           const float* __restrict__ W2, const float* __restrict__ b2)
{
    extern __shared__ float sm[];
    float*    sA  = sm + SA_OFF;                 // fp32 [128][68]
    uint32_t* sW1 = (uint32_t*)(sm + SW1_OFF);   // tf32 [64][136]
    uint32_t* sH  = (uint32_t*)(sm + SH_OFF);    // tf32 [128][132]
    uint32_t* sW2 = (uint32_t*)(sm + SW2_OFF);   // tf32 [128][72]
    float*    sB1 = sm + SB1_OFF;
    float*    sB2 = sm + SB2_OFF;

    const int tid  = threadIdx.x;
    const int lane = tid & 31;
    const int warp = tid >> 5;
    const int gid  = lane >> 2;     // 0..7
    const int tig  = lane & 3;      // 0..3
    const size_t base = (size_t)blockIdx.x * 128;

    for (int t = tid; t < 64*DHH; t += 256) {
        int k = t >> 7, u = t & 127;
        sW1[k*136 + u] = f2tf32(W1[t]);
    }
    for (int t = tid; t < DHH*64; t += 256) {
        int u = t >> 6, nn2 = t & 63;
        sW2[u*72 + nn2] = f2tf32(W2[t]);
    }
    if (tid < 128) sB1[tid] = b1[tid];
    if (tid < 64)  sB2[tid] = b2[tid];

    // coalesced tile load: consecutive threads -> consecutive float4s
    for (int t = tid; t < 128*16; t += 256) {
        int row = t >> 4, q = t & 15;
        float4 v = *(const float4*)(eio + (base + row)*64 + q*4);
        *(float4*)(sA + row*68 + q*4) = v;
    }
    __syncthreads();

    const int row0 = warp*16 + gid;      // this thread's rows: row0, row0+8
    const int row1 = row0 + 8;

    // A fragments for GEMM1, converted once (32 regs)
    uint32_t af0[8], af1[8], af2[8], af3[8];
    #pragma unroll
    for (int kt = 0; kt < 8; kt++) {
        int c0 = kt*8 + tig;
        af0[kt] = f2tf32(sA[row0*68 + c0]);
        af1[kt] = f2tf32(sA[row1*68 + c0]);
        af2[kt] = f2tf32(sA[row0*68 + c0 + 4]);
        af3[kt] = f2tf32(sA[row1*68 + c0 + 4]);
    }

    // ---------------- GEMM1: H = relu(A @ W1 + b1), N in 4 chunks of 32 ----
    #pragma unroll
    for (int nc = 0; nc < 4; nc++) {
        float a00=0,a01=0,a02=0,a03=0;
        float a10=0,a11=0,a12=0,a13=0;
        float a20=0,a21=0,a22=0,a23=0;
        float a30=0,a31=0,a32=0,a33=0;
        #pragma unroll
        for (int kt = 0; kt < 8; kt++) {
            const uint32_t* w = sW1 + (kt*8 + tig)*136 + nc*32 + gid;
            uint32_t b00 = w[0],    b01 = w[4*136];
            uint32_t b10 = w[8],    b11 = w[4*136 + 8];
            uint32_t b20 = w[16],   b21 = w[4*136 + 16];
            uint32_t b30 = w[24],   b31 = w[4*136 + 24];
            mma_tf32(a00,a01,a02,a03, af0[kt],af1[kt],af2[kt],af3[kt], b00,b01);
            mma_tf32(a10,a11,a12,a13, af0[kt],af1[kt],af2[kt],af3[kt], b10,b11);
            mma_tf32(a20,a21,a22,a23, af0[kt],af1[kt],af2[kt],af3[kt], b20,b21);
            mma_tf32(a30,a31,a32,a33, af0[kt],af1[kt],af2[kt],af3[kt], b30,b31);
        }
        #pragma unroll
        for (int nt = 0; nt < 4; nt++) {
            float c0v, c1v, c2v, c3v;
            if (nt == 0)      { c0v=a00; c1v=a01; c2v=a02; c3v=a03; }
            else if (nt == 1) { c0v=a10; c1v=a11; c2v=a12; c3v=a13; }
            else if (nt == 2) { c0v=a20; c1v=a21; c2v=a22; c3v=a23; }
            else              { c0v=a30; c1v=a31; c2v=a32; c3v=a33; }
            int c = nc*32 + nt*8 + 2*tig;
            float bb0 = sB1[c], bb1 = sB1[c+1];
            sH[row0*132 + c    ] = f2tf32(fmaxf(c0v + bb0, 0.f));
            sH[row0*132 + c + 1] = f2tf32(fmaxf(c1v + bb1, 0.f));
            sH[row1*132 + c    ] = f2tf32(fmaxf(c2v + bb0, 0.f));
            sH[row1*132 + c + 1] = f2tf32(fmaxf(c3v + bb1, 0.f));
        }
    }
    __syncwarp();   // warp-private sH rows: warp sync suffices

    // ---------------- GEMM2: O = H @ W2 + b2, N in 2 chunks of 32 ----------
    #pragma unroll
    for (int nc = 0; nc < 2; nc++) {
        float a00=0,a01=0,a02=0,a03=0;
        float a10=0,a11=0,a12=0,a13=0;
        float a20=0,a21=0,a22=0,a23=0;
        float a30=0,a31=0,a32=0,a33=0;
        #pragma unroll
        for (int kt = 0; kt < 16; kt++) {
            int c0 = kt*8 + tig;
            uint32_t h0 = sH[row0*132 + c0];
            uint32_t h1 = sH[row1*132 + c0];
            uint32_t h2 = sH[row0*132 + c0 + 4];
            uint32_t h3 = sH[row1*132 + c0 + 4];
            const uint32_t* w = sW2 + c0*72 + nc*32 + gid;
            uint32_t b00 = w[0],  b01 = w[4*72];
            uint32_t b10 = w[8],  b11 = w[4*72 + 8];
            uint32_t b20 = w[16], b21 = w[4*72 + 16];
            uint32_t b30 = w[24], b31 = w[4*72 + 24];
            mma_tf32(a00,a01,a02,a03, h0,h1,h2,h3, b00,b01);
            mma_tf32(a10,a11,a12,a13, h0,h1,h2,h3, b10,b11);
            mma_tf32(a20,a21,a22,a23, h0,h1,h2,h3, b20,b21);
            mma_tf32(a30,a31,a32,a33, h0,h1,h2,h3, b30,b31);
        }
        #pragma unroll
        for (int nt = 0; nt < 4; nt++) {
            float c0v, c1v, c2v, c3v;
            if (nt == 0)      { c0v=a00; c1v=a01; c2v=a02; c3v=a03; }
            else if (nt == 1) { c0v=a10; c1v=a11; c2v=a12; c3v=a13; }
            else if (nt == 2) { c0v=a20; c1v=a21; c2v=a22; c3v=a23; }
            else              { c0v=a30; c1v=a31; c2v=a32; c3v=a33; }
            int c = nc*32 + nt*8 + 2*tig;
            float b20v = sB2[c], b21v = sB2[c+1];
            float r00 = sA[row0*68 + c    ] + fmaxf(c0v + b20v, 0.f);
            float r01 = sA[row0*68 + c + 1] + fmaxf(c1v + b21v, 0.f);
            float r10 = sA[row1*68 + c    ] + fmaxf(c2v + b20v, 0.f);
            float r11 = sA[row1*68 + c + 1] + fmaxf(c3v + b21v, 0.f);
            *(float2*)(eio + (base + row0)*64 + c) = make_float2(r00, r01);
            *(float2*)(eio + (base + row1)*64 + c) = make_float2(r10, r11);
        }
    }
}

// ---------------------------------------------------------------------------
// K4: node finish.
// ---------------------------------------------------------------------------
__global__ void k_node_finish(const float* __restrict__ Wo_n,
                              const float* __restrict__ lng,
                              const float* __restrict__ lnb,
                              const float* __restrict__ W1,
                              const float* __restrict__ Bi1,
                              const float* __restrict__ W2,
                              const float* __restrict__ Bi2,
                              float* __restrict__ n_out)
{
    int row = blockIdx.x;
    int o = threadIdx.x;
    __shared__ float svc[DD];
    __shared__ float sn2[DD];
    __shared__ float sn3[DD];
    __shared__ float sh[DHH];
    svc[o] = g_vc[row*DD + o];
    __syncthreads();
    float acc = 0.f;
    #pragma unroll
    for (int k = 0; k < DD; k++) acc += svc[k]*Wo_n[k*DD + o];
    float n2 = g_n1[row*DD + o] + acc;
    sn2[o] = n2;
    __syncthreads();
    float s = 0.f;
    #pragma unroll
    for (int k = 0; k < DD; k++) s += sn2[k];
    float m = s*(1.f/DD);
    float v = 0.f;
    #pragma unroll
    for (int k = 0; k < DD; k++) { float d = sn2[k]-m; v += d*d; }
    v *= (1.f/DD);
    float rstd = rsqrtf(v + 1e-5f);
    float n3 = (n2-m)*rstd*lng[o] + lnb[o];
    sn3[o] = n3;
    __syncthreads();
    #pragma unroll
    for (int uu = 0; uu < 2; uu++) {
        int u = o + uu*64;
        float h = Bi1[u];
        #pragma unroll
        for (int k = 0; k < DD; k++) h += sn3[k]*W1[k*DHH + u];
        sh[u] = fmaxf(h, 0.f);
    }
    __syncthreads();
    float oacc = Bi2[o];
    #pragma unroll
    for (int u = 0; u < DHH; u++) oacc += sh[u]*W2[u*DD + o];
    n_out[row*DD + o] = n3 + fmaxf(oacc, 0.f);
}

extern "C" void kernel_launch(void* const* d_in, const int* in_sizes, int n_in,
                              void* d_out, int out_size)
{
    const float* n       = (const float*)d_in[0];
    const float* e       = (const float*)d_in[1];
    const float* Wq      = (const float*)d_in[2];
    const float* Wk      = (const float*)d_in[3];
    const float* Wv      = (const float*)d_in[4];
    const float* Wo_n    = (const float*)d_in[5];
    const float* We      = (const float*)d_in[6];
    const float* Wg      = (const float*)d_in[7];
    const float* Wo_e    = (const float*)d_in[8];
    const float* ln_n1_g = (const float*)d_in[9];
    const float* ln_n1_b = (const float*)d_in[10];
    const float* ln_e1_g = (const float*)d_in[11];
    const float* ln_e1_b = (const float*)d_in[12];
    const float* ln_n2_g = (const float*)d_in[13];
    const float* ln_n2_b = (const float*)d_in[14];
    const float* ln_e2_g = (const float*)d_in[15];
    const float* ln_e2_b = (const float*)d_in[16];
    const float* mn_w1   = (const float*)d_in[17];
    const float* mn_b1   = (const float*)d_in[18];
    const float* mn_w2   = (const float*)d_in[19];
    const float* mn_b2   = (const float*)d_in[20];
    const float* me_w1   = (const float*)d_in[21];
    const float* me_b1   = (const float*)d_in[22];
    const float* me_w2   = (const float*)d_in[23];
    const float* me_b2   = (const float*)d_in[24];

    float* out   = (float*)d_out;
    float* n_out = out;
    float* e_out = out + BB*NN*DD;

    cudaFuncSetAttribute(k_edge, cudaFuncAttributeMaxDynamicSharedMemorySize, EDGE_SMEM_BYTES);
    cudaFuncSetAttribute(k_edge_mlp, cudaFuncAttributeMaxDynamicSharedMemorySize, MLP_SMEM_BYTES);

    k_node_prep<<<BB*NN, 64>>>(n, Wq, Wk, Wv, ln_n1_g, ln_n1_b);

    dim3 grid(NN, BB);
    k_edge<<<grid, 256, EDGE_SMEM_BYTES>>>(e, We, Wg, Wo_e,
                                           ln_e1_g, ln_e1_b, ln_e2_g, ln_e2_b,
                                           e_out);

    k_edge_mlp<<<(BB*NN*NN)/128, 256, MLP_SMEM_BYTES>>>(e_out, me_w1, me_b1, me_w2, me_b2);

    k_node_finish<<<BB*NN, 64>>>(Wo_n, ln_n2_g, ln_n2_b,
                                 mn_w1, mn_b1, mn_w2, mn_b2, n_out);
}

// round 10
// speedup vs baseline: 1.8171x; 1.2385x over previous
#include <cuda_runtime.h>
#include <math.h>
#include <stdint.h>

#define BB 2
#define NN 512
#define DD 64
#define HH 8
#define DHH 128

// ----------------- k_edge smem layout (floats) -----------------
#define OFF_ELOG   0        // 8*520 = 4160
#define OFF_WEP    4160     // 512  (g1-scaled We)
#define OFF_WGP    4672     // 512  (g1-scaled Wg)
#define OFF_Q      5184     // 64
#define OFF_SE     5248     // 8
#define OFF_CE     5256     // 8
#define OFF_SG     5264     // 8
#define OFF_CG     5272     // 8
#define OFF_CENT   5280     // 8
#define OFF_WPART  5288     // 64
#define EDGE_SMEM_FLOATS 5352
#define EDGE_SMEM_BYTES  (EDGE_SMEM_FLOATS*4)

// ----------------- K3 (finish + mlp) smem layout (floats) -----------------
#define KA_OFF    0          // sA   128 x 68 fp32 (8704)
#define KW1_OFF   8704       // sW1  64 x 136 tf32
#define KH_OFF    17408      // sH   128 x 132 tf32
#define KW2_OFF   34304      // sW2  128 x 72 tf32
#define KB1_OFF   43520      // 128
#define KB2_OFF   43648      // 64
#define KWOE_OFF  43712      // 512  (Wo_e [8][64])
#define KEL_OFF   44224      // 1024 (Elog slice [8][128])
#define KG1_OFF   45248      // 64
#define KBE1_OFF  45312      // 64
#define KG2_OFF   45376      // 64
#define KBE2_OFF  45440      // 64
#define K3_SMEM_FLOATS 45504
#define K3_SMEM_BYTES  (K3_SMEM_FLOATS*4)   // 182016 B

__device__ __align__(16) float g_n1[BB*NN*DD];
__device__ __align__(16) float g_q [BB*NN*DD];
__device__ __align__(16) float g_k [BB*NN*DD];
__device__ __align__(16) float g_v [BB*NN*DD];
__device__ __align__(16) float g_vc[BB*NN*DD];
__device__ __align__(16) float g_elog[(size_t)BB*HH*NN*NN];   // 16.8 MB

__device__ __forceinline__ uint32_t f2tf32(float x) {
    uint32_t r;
    asm("cvt.rna.tf32.f32 %0, %1;" : "=r"(r) : "f"(x));
    return r;
}

__device__ __forceinline__ void mma_tf32(float& c0, float& c1, float& c2, float& c3,
                                         uint32_t a0, uint32_t a1,
                                         uint32_t a2, uint32_t a3,
                                         uint32_t b0, uint32_t b1) {
    asm volatile(
        "mma.sync.aligned.m16n8k8.row.col.f32.tf32.tf32.f32 "
        "{%0,%1,%2,%3},{%4,%5,%6,%7},{%8,%9},{%0,%1,%2,%3};"
        : "+f"(c0), "+f"(c1), "+f"(c2), "+f"(c3)
        : "r"(a0), "r"(a1), "r"(a2), "r"(a3), "r"(b0), "r"(b1));
}

// ---------------------------------------------------------------------------
// K1: node LN + Q/K/V projection.
// ---------------------------------------------------------------------------
__global__ void k_node_prep(const float* __restrict__ n,
                            const float* __restrict__ Wq,
                            const float* __restrict__ Wk,
                            const float* __restrict__ Wv,
                            const float* __restrict__ lng,
                            const float* __restrict__ lnb)
{
    int row = blockIdx.x;
    int o = threadIdx.x;
    __shared__ float sx[DD];
    __shared__ float sn1[DD];
    sx[o] = n[row*DD + o];
    __syncthreads();
    float s = 0.f;
    #pragma unroll
    for (int k = 0; k < DD; k++) s += sx[k];
    float m = s * (1.f/DD);
    float v = 0.f;
    #pragma unroll
    for (int k = 0; k < DD; k++) { float d = sx[k]-m; v += d*d; }
    v *= (1.f/DD);
    float rstd = rsqrtf(v + 1e-5f);
    float n1 = (sx[o]-m)*rstd*lng[o] + lnb[o];
    sn1[o] = n1;
    g_n1[row*DD + o] = n1;
    __syncthreads();
    float q = 0.f, kk = 0.f, vv = 0.f;
    #pragma unroll
    for (int k = 0; k < DD; k++) {
        float a = sn1[k];
        q  += a * Wq[k*DD + o];
        kk += a * Wk[k*DD + o];
        vv += a * Wv[k*DD + o];
    }
    g_q[row*DD + o] = q;
    g_k[row*DD + o] = kk;
    g_v[row*DD + o] = vv;
}

// ---------------------------------------------------------------------------
// K2: edge attention, streaming pass (LN folded into weights).
// Writes Elog to g_elog and vc to g_vc. grid=(N,B), 256 threads.
// ---------------------------------------------------------------------------
__global__ void __launch_bounds__(256, 1)
k_edge(const float* __restrict__ e,
       const float* __restrict__ We, const float* __restrict__ Wg,
       const float* __restrict__ lg1, const float* __restrict__ lb1)
{
    extern __shared__ float sm[];
    float* sElog  = sm + OFF_ELOG;
    float* sWeP   = sm + OFF_WEP;
    float* sWgP   = sm + OFF_WGP;
    float* sQ     = sm + OFF_Q;
    float* sSe    = sm + OFF_SE;
    float* sCe    = sm + OFF_CE;
    float* sSg    = sm + OFF_SG;
    float* sCg    = sm + OFF_CG;
    float* sCent  = sm + OFF_CENT;
    float* sWpart = sm + OFF_WPART;

    const int i    = blockIdx.x;
    const int b    = blockIdx.y;
    const int tid  = threadIdx.x;
    const int lane = tid & 31;
    const int warp = tid >> 5;
    const int rowbn = b*NN + i;

    for (int t = tid; t < 512; t += 256) {
        int k = t >> 3;
        float g = lg1[k];
        sWeP[t] = g * We[t];
        sWgP[t] = g * Wg[t];
    }
    if (tid < 64) sQ[tid] = g_q[rowbn*DD + tid];
    __syncthreads();
    if (tid < 8) {
        float se=0.f, ce=0.f, sg=0.f, cg=0.f;
        for (int k = 0; k < 64; k++) {
            float bb = lb1[k];
            se += sWeP[k*8 + tid];
            sg += sWgP[k*8 + tid];
            ce += bb * We[k*8 + tid];
            cg += bb * Wg[k*8 + tid];
        }
        sSe[tid]=se; sCe[tid]=ce; sSg[tid]=sg; sCg[tid]=cg;
    }
    __syncthreads();

    const float* erow = e + (size_t)rowbn * NN * DD;
    const float scale = 0.35355339059327373f;

    float gacc[HH];
    #pragma unroll
    for (int h = 0; h < HH; h++) gacc[h] = 0.f;

    #pragma unroll
    for (int jj = 0; jj < 2; jj++) {
        const int j = tid + jj*256;
        const float4* xp = (const float4*)(erow + j*DD);
        const float4* kp = (const float4*)(g_k + (b*NN + j)*DD);
        const float4* qp = (const float4*)sQ;

        float s = 0.f, sq = 0.f;
        float Eh[HH], Gh[HH], ac[HH];
        #pragma unroll
        for (int h = 0; h < HH; h++) { Eh[h]=0.f; Gh[h]=0.f; ac[h]=0.f; }

        #pragma unroll
        for (int q = 0; q < 16; q++) {
            float4 xv = xp[q];
            float4 kv = kp[q];
            float4 qv = qp[q];
            s  += (xv.x + xv.y) + (xv.z + xv.w);
            sq += (xv.x*xv.x + xv.y*xv.y) + (xv.z*xv.z + xv.w*xv.w);
            ac[q>>1] += qv.x*kv.x + qv.y*kv.y + qv.z*kv.z + qv.w*kv.w;
            float xs[4] = {xv.x, xv.y, xv.z, xv.w};
            #pragma unroll
            for (int c = 0; c < 4; c++) {
                int k = q*4 + c;
                float xk = xs[c];
                const float4* we = (const float4*)(sWeP + k*8);
                const float4* wg = (const float4*)(sWgP + k*8);
                float4 a0 = we[0], a1 = we[1];
                float4 c0 = wg[0], c1 = wg[1];
                Eh[0]+=xk*a0.x; Eh[1]+=xk*a0.y; Eh[2]+=xk*a0.z; Eh[3]+=xk*a0.w;
                Eh[4]+=xk*a1.x; Eh[5]+=xk*a1.y; Eh[6]+=xk*a1.z; Eh[7]+=xk*a1.w;
                Gh[0]+=xk*c0.x; Gh[1]+=xk*c0.y; Gh[2]+=xk*c0.z; Gh[3]+=xk*c0.w;
                Gh[4]+=xk*c1.x; Gh[5]+=xk*c1.y; Gh[6]+=xk*c1.z; Gh[7]+=xk*c1.w;
            }
        }

        float m = s * (1.f/64.f);
        float var = sq * (1.f/64.f) - m*m;
        float rstd = rsqrtf(var + 1e-5f);

        float* gEl = g_elog + (((size_t)b*HH)*NN + i)*NN + j;
        #pragma unroll
        for (int h = 0; h < HH; h++) {
            float E = rstd*(Eh[h] - m*sSe[h]) + sCe[h];
            float G = rstd*(Gh[h] - m*sSg[h]) + sCg[h];
            float a = fminf(fmaxf(ac[h]*scale, -5.f), 5.f);
            float el = a + E;
            sElog[h*520 + j] = el;
            gEl[(size_t)h*NN*NN] = el;
            gacc[h] += 1.f/(1.f + expf(-G));
        }
    }

    #pragma unroll
    for (int h = 0; h < HH; h++) {
        #pragma unroll
        for (int off = 16; off > 0; off >>= 1)
            gacc[h] += __shfl_xor_sync(0xffffffffu, gacc[h], off);
    }
    if (lane == 0) {
        #pragma unroll
        for (int h = 0; h < HH; h++) sWpart[warp*8 + h] = gacc[h];
    }
    __syncthreads();
    if (tid < 8) {
        float s = 0.f;
        #pragma unroll
        for (int w = 0; w < 8; w++) s += sWpart[w*8 + tid];
        sCent[tid] = log1pf(s);
    }
    __syncthreads();

    {
        const int h = warp;
        const float* el = sElog + h*520;
        float mmax = -1e30f;
        for (int j = lane; j < NN; j += 32) mmax = fmaxf(mmax, el[j]);
        #pragma unroll
        for (int off = 16; off > 0; off >>= 1)
            mmax = fmaxf(mmax, __shfl_xor_sync(0xffffffffu, mmax, off));

        float denom = 0.f;
        float p0=0,p1=0,p2=0,p3=0,p4=0,p5=0,p6=0,p7=0;
        for (int j = lane; j < NN; j += 32) {
            float t = expf(el[j] - mmax);
            denom += t;
            const float4* vp = (const float4*)(g_v + (b*NN + j)*DD + h*8);
            float4 va = vp[0], vb = vp[1];
            p0 += t*va.x; p1 += t*va.y; p2 += t*va.z; p3 += t*va.w;
            p4 += t*vb.x; p5 += t*vb.y; p6 += t*vb.z; p7 += t*vb.w;
        }
        #pragma unroll
        for (int off = 16; off > 0; off >>= 1) {
            denom += __shfl_xor_sync(0xffffffffu, denom, off);
            p0 += __shfl_xor_sync(0xffffffffu, p0, off);
            p1 += __shfl_xor_sync(0xffffffffu, p1, off);
            p2 += __shfl_xor_sync(0xffffffffu, p2, off);
            p3 += __shfl_xor_sync(0xffffffffu, p3, off);
            p4 += __shfl_xor_sync(0xffffffffu, p4, off);
            p5 += __shfl_xor_sync(0xffffffffu, p5, off);
            p6 += __shfl_xor_sync(0xffffffffu, p6, off);
            p7 += __shfl_xor_sync(0xffffffffu, p7, off);
        }
        if (lane == 0) {
            float c = sCent[h] / denom;
            float* dst = g_vc + rowbn*DD + h*8;
            dst[0]=p0*c; dst[1]=p1*c; dst[2]=p2*c; dst[3]=p3*c;
            dst[4]=p4*c; dst[5]=p5*c; dst[6]=p6*c; dst[7]=p7*c;
        }
    }
}

// ---------------------------------------------------------------------------
// K3: fused edge finish + MLP. tile = 128 edges of one (b,i) row.
// e3 = LN2( LN1(e) + Elog @ Wo_e ) computed in smem; then tf32 mma MLP;
// out = e3 + relu(mlp(e3)). grid = (4*N, B), 256 threads.
// ---------------------------------------------------------------------------
__global__ void __launch_bounds__(256, 1)
k_edge_finish_mlp(const float* __restrict__ e,
                  const float* __restrict__ WoE,
                  const float* __restrict__ lg1, const float* __restrict__ lb1,
                  const float* __restrict__ lg2, const float* __restrict__ lb2,
                  const float* __restrict__ W1, const float* __restrict__ b1,
                  const float* __restrict__ W2, const float* __restrict__ b2,
                  float* __restrict__ e_out)
{
    extern __shared__ float sm[];
    float*    sA   = sm + KA_OFF;                 // fp32 [128][68]
    uint32_t* sW1  = (uint32_t*)(sm + KW1_OFF);   // tf32 [64][136]
    uint32_t* sH   = (uint32_t*)(sm + KH_OFF);    // tf32 [128][132]
    uint32_t* sW2  = (uint32_t*)(sm + KW2_OFF);   // tf32 [128][72]
    float*    sB1  = sm + KB1_OFF;
    float*    sB2  = sm + KB2_OFF;
    float*    sWoe = sm + KWOE_OFF;               // [8][64]
    float*    sEl  = sm + KEL_OFF;                // [8][128]
    float*    sG1  = sm + KG1_OFF;
    float*    sBe1 = sm + KBE1_OFF;
    float*    sG2  = sm + KG2_OFF;
    float*    sBe2 = sm + KBE2_OFF;

    const int tid  = threadIdx.x;
    const int lane = tid & 31;
    const int warp = tid >> 5;
    const int gid  = lane >> 2;
    const int tig  = lane & 3;

    const int bx = blockIdx.x;
    const int jc = bx & 3;
    const int i  = bx >> 2;
    const int b  = blockIdx.y;
    const int rowbn = b*NN + i;
    const size_t gj0 = (size_t)rowbn*NN + jc*128;   // first global edge row

    // weights + params
    for (int t = tid; t < 64*DHH; t += 256) {
        int k = t >> 7, u = t & 127;
        sW1[k*136 + u] = f2tf32(W1[t]);
    }
    for (int t = tid; t < DHH*64; t += 256) {
        int u = t >> 6, c = t & 63;
        sW2[u*72 + c] = f2tf32(W2[t]);
    }
    for (int t = tid; t < 512; t += 256) sWoe[t] = WoE[t];
    if (tid < 128) sB1[tid] = b1[tid];
    if (tid < 64) {
        sB2[tid]  = b2[tid];
        sG1[tid]  = lg1[tid]; sBe1[tid] = lb1[tid];
        sG2[tid]  = lg2[tid]; sBe2[tid] = lb2[tid];
    }
    // Elog slice [8][128]
    for (int t = tid; t < 1024; t += 256) {
        int h = t >> 7, jl = t & 127;
        sEl[h*128 + jl] = g_elog[(((size_t)b*HH + h)*NN + i)*NN + jc*128 + jl];
    }
    // x tile
    for (int t = tid; t < 128*16; t += 256) {
        int row = t >> 4, q = t & 15;
        float4 v = *(const float4*)(e + (gj0 + row)*DD + q*4);
        *(float4*)(sA + row*68 + q*4) = v;
    }
    __syncthreads();

    // ---------------- phase A: e3 = LN2( LN1(x) + El @ WoE ) in sA ---------
    {
        const int r    = tid >> 1;
        const int half = tid & 1;
        const int c0   = half*32;

        float s = 0.f, sq = 0.f;
        #pragma unroll
        for (int c = 0; c < 32; c++) {
            float v = sA[r*68 + c0 + c];
            s += v; sq += v*v;
        }
        s  += __shfl_xor_sync(0xffffffffu, s, 1);
        sq += __shfl_xor_sync(0xffffffffu, sq, 1);
        float m = s*(1.f/64.f);
        float rstd = rsqrtf(sq*(1.f/64.f) - m*m + 1e-5f);

        float el0=sEl[r], el1=sEl[128+r], el2=sEl[256+r], el3=sEl[384+r];
        float el4=sEl[512+r], el5=sEl[640+r], el6=sEl[768+r], el7=sEl[896+r];

        float y[32];
        #pragma unroll
        for (int c = 0; c < 32; c++) {
            int k = c0 + c;
            float x = sA[r*68 + k];
            float a = (x - m)*rstd*sG1[k] + sBe1[k];
            a += el0*sWoe[k]       + el1*sWoe[64 + k]
               + el2*sWoe[128 + k] + el3*sWoe[192 + k]
               + el4*sWoe[256 + k] + el5*sWoe[320 + k]
               + el6*sWoe[384 + k] + el7*sWoe[448 + k];
            y[c] = a;
        }
        float s2 = 0.f, q2 = 0.f;
        #pragma unroll
        for (int c = 0; c < 32; c++) { s2 += y[c]; q2 += y[c]*y[c]; }
        s2 += __shfl_xor_sync(0xffffffffu, s2, 1);
        q2 += __shfl_xor_sync(0xffffffffu, q2, 1);
        float m2 = s2*(1.f/64.f);
        float rstd2 = rsqrtf(q2*(1.f/64.f) - m2*m2 + 1e-5f);
        #pragma unroll
        for (int c = 0; c < 32; c++) {
            int k = c0 + c;
            sA[r*68 + k] = (y[c] - m2)*rstd2*sG2[k] + sBe2[k];
        }
    }
    __syncthreads();

    // ---------------- phase B: tf32 mma MLP on sA ---------------------------
    const int row0 = warp*16 + gid;
    const int row1 = row0 + 8;

    uint32_t af0[8], af1[8], af2[8], af3[8];
    #pragma unroll
    for (int kt = 0; kt < 8; kt++) {
        int c0 = kt*8 + tig;
        af0[kt] = f2tf32(sA[row0*68 + c0]);
        af1[kt] = f2tf32(sA[row1*68 + c0]);
        af2[kt] = f2tf32(sA[row0*68 + c0 + 4]);
        af3[kt] = f2tf32(sA[row1*68 + c0 + 4]);
    }

    // GEMM1: H = relu(A @ W1 + b1), N in 4 chunks of 32
    #pragma unroll
    for (int nc = 0; nc < 4; nc++) {
        float a00=0,a01=0,a02=0,a03=0;
        float a10=0,a11=0,a12=0,a13=0;
        float a20=0,a21=0,a22=0,a23=0;
        float a30=0,a31=0,a32=0,a33=0;
        #pragma unroll
        for (int kt = 0; kt < 8; kt++) {
            const uint32_t* w = sW1 + (kt*8 + tig)*136 + nc*32 + gid;
            uint32_t b00 = w[0],    b01 = w[4*136];
            uint32_t b10 = w[8],    b11 = w[4*136 + 8];
            uint32_t b20 = w[16],   b21 = w[4*136 + 16];
            uint32_t b30 = w[24],   b31 = w[4*136 + 24];
            mma_tf32(a00,a01,a02,a03, af0[kt],af1[kt],af2[kt],af3[kt], b00,b01);
            mma_tf32(a10,a11,a12,a13, af0[kt],af1[kt],af2[kt],af3[kt], b10,b11);
            mma_tf32(a20,a21,a22,a23, af0[kt],af1[kt],af2[kt],af3[kt], b20,b21);
            mma_tf32(a30,a31,a32,a33, af0[kt],af1[kt],af2[kt],af3[kt], b30,b31);
        }
        #pragma unroll
        for (int nt = 0; nt < 4; nt++) {
            float c0v, c1v, c2v, c3v;
            if (nt == 0)      { c0v=a00; c1v=a01; c2v=a02; c3v=a03; }
            else if (nt == 1) { c0v=a10; c1v=a11; c2v=a12; c3v=a13; }
            else if (nt == 2) { c0v=a20; c1v=a21; c2v=a22; c3v=a23; }
            else              { c0v=a30; c1v=a31; c2v=a32; c3v=a33; }
            int c = nc*32 + nt*8 + 2*tig;
            float bb0 = sB1[c], bb1 = sB1[c+1];
            sH[row0*132 + c    ] = f2tf32(fmaxf(c0v + bb0, 0.f));
            sH[row0*132 + c + 1] = f2tf32(fmaxf(c1v + bb1, 0.f));
            sH[row1*132 + c    ] = f2tf32(fmaxf(c2v + bb0, 0.f));
            sH[row1*132 + c + 1] = f2tf32(fmaxf(c3v + bb1, 0.f));
        }
    }
    __syncwarp();

    // GEMM2: O = H @ W2 + b2, N in 2 chunks of 32
    #pragma unroll
    for (int nc = 0; nc < 2; nc++) {
        float a00=0,a01=0,a02=0,a03=0;
        float a10=0,a11=0,a12=0,a13=0;
        float a20=0,a21=0,a22=0,a23=0;
        float a30=0,a31=0,a32=0,a33=0;
        #pragma unroll
        for (int kt = 0; kt < 16; kt++) {
            int c0 = kt*8 + tig;
            uint32_t h0 = sH[row0*132 + c0];
            uint32_t h1 = sH[row1*132 + c0];
            uint32_t h2 = sH[row0*132 + c0 + 4];
            uint32_t h3 = sH[row1*132 + c0 + 4];
            const uint32_t* w = sW2 + c0*72 + nc*32 + gid;
            uint32_t b00 = w[0],  b01 = w[4*72];
            uint32_t b10 = w[8],  b11 = w[4*72 + 8];
            uint32_t b20 = w[16], b21 = w[4*72 + 16];
            uint32_t b30 = w[24], b31 = w[4*72 + 24];
            mma_tf32(a00,a01,a02,a03, h0,h1,h2,h3, b00,b01);
            mma_tf32(a10,a11,a12,a13, h0,h1,h2,h3, b10,b11);
            mma_tf32(a20,a21,a22,a23, h0,h1,h2,h3, b20,b21);
            mma_tf32(a30,a31,a32,a33, h0,h1,h2,h3, b30,b31);
        }
        #pragma unroll
        for (int nt = 0; nt < 4; nt++) {
            float c0v, c1v, c2v, c3v;
            if (nt == 0)      { c0v=a00; c1v=a01; c2v=a02; c3v=a03; }
            else if (nt == 1) { c0v=a10; c1v=a11; c2v=a12; c3v=a13; }
            else if (nt == 2) { c0v=a20; c1v=a21; c2v=a22; c3v=a23; }
            else              { c0v=a30; c1v=a31; c2v=a32; c3v=a33; }
            int c = nc*32 + nt*8 + 2*tig;
            float b20v = sB2[c], b21v = sB2[c+1];
            float r00 = sA[row0*68 + c    ] + fmaxf(c0v + b20v, 0.f);
            float r01 = sA[row0*68 + c + 1] + fmaxf(c1v + b21v, 0.f);
            float r10 = sA[row1*68 + c    ] + fmaxf(c2v + b20v, 0.f);
            float r11 = sA[row1*68 + c + 1] + fmaxf(c3v + b21v, 0.f);
            *(float2*)(e_out + (gj0 + row0)*DD + c) = make_float2(r00, r01);
            *(float2*)(e_out + (gj0 + row1)*DD + c) = make_float2(r10, r11);
        }
    }
}

// ---------------------------------------------------------------------------
// K4: node finish.
// ---------------------------------------------------------------------------
__global__ void k_node_finish(const float* __restrict__ Wo_n,
                              const float* __restrict__ lng,
                              const float* __restrict__ lnb,
                              const float* __restrict__ W1,
                              const float* __restrict__ Bi1,
                              const float* __restrict__ W2,
                              const float* __restrict__ Bi2,
                              float* __restrict__ n_out)
{
    int row = blockIdx.x;
    int o = threadIdx.x;
    __shared__ float svc[DD];
    __shared__ float sn2[DD];
    __shared__ float sn3[DD];
    __shared__ float sh[DHH];
    svc[o] = g_vc[row*DD + o];
    __syncthreads();
    float acc = 0.f;
    #pragma unroll
    for (int k = 0; k < DD; k++) acc += svc[k]*Wo_n[k*DD + o];
    float n2 = g_n1[row*DD + o] + acc;
    sn2[o] = n2;
    __syncthreads();
    float s = 0.f;
    #pragma unroll
    for (int k = 0; k < DD; k++) s += sn2[k];
    float m = s*(1.f/DD);
    float v = 0.f;
    #pragma unroll
    for (int k = 0; k < DD; k++) { float d = sn2[k]-m; v += d*d; }
    v *= (1.f/DD);
    float rstd = rsqrtf(v + 1e-5f);
    float n3 = (n2-m)*rstd*lng[o] + lnb[o];
    sn3[o] = n3;
    __syncthreads();
    #pragma unroll
    for (int uu = 0; uu < 2; uu++) {
        int u = o + uu*64;
        float h = Bi1[u];
        #pragma unroll
        for (int k = 0; k < DD; k++) h += sn3[k]*W1[k*DHH + u];
        sh[u] = fmaxf(h, 0.f);
    }
    __syncthreads();
    float oacc = Bi2[o];
    #pragma unroll
    for (int u = 0; u < DHH; u++) oacc += sh[u]*W2[u*DD + o];
    n_out[row*DD + o] = n3 + fmaxf(oacc, 0.f);
}

extern "C" void kernel_launch(void* const* d_in, const int* in_sizes, int n_in,
                              void* d_out, int out_size)
{
    const float* n       = (const float*)d_in[0];
    const float* e       = (const float*)d_in[1];
    const float* Wq      = (const float*)d_in[2];
    const float* Wk      = (const float*)d_in[3];
    const float* Wv      = (const float*)d_in[4];
    const float* Wo_n    = (const float*)d_in[5];
    const float* We      = (const float*)d_in[6];
    const float* Wg      = (const float*)d_in[7];
    const float* Wo_e    = (const float*)d_in[8];
    const float* ln_n1_g = (const float*)d_in[9];
    const float* ln_n1_b = (const float*)d_in[10];
    const float* ln_e1_g = (const float*)d_in[11];
    const float* ln_e1_b = (const float*)d_in[12];
    const float* ln_n2_g = (const float*)d_in[13];
    const float* ln_n2_b = (const float*)d_in[14];
    const float* ln_e2_g = (const float*)d_in[15];
    const float* ln_e2_b = (const float*)d_in[16];
    const float* mn_w1   = (const float*)d_in[17];
    const float* mn_b1   = (const float*)d_in[18];
    const float* mn_w2   = (const float*)d_in[19];
    const float* mn_b2   = (const float*)d_in[20];
    const float* me_w1   = (const float*)d_in[21];
    const float* me_b1   = (const float*)d_in[22];
    const float* me_w2   = (const float*)d_in[23];
    const float* me_b2   = (const float*)d_in[24];

    float* out   = (float*)d_out;
    float* n_out = out;
    float* e_out = out + BB*NN*DD;

    cudaFuncSetAttribute(k_edge, cudaFuncAttributeMaxDynamicSharedMemorySize, EDGE_SMEM_BYTES);
    cudaFuncSetAttribute(k_edge_finish_mlp, cudaFuncAttributeMaxDynamicSharedMemorySize, K3_SMEM_BYTES);

    k_node_prep<<<BB*NN, 64>>>(n, Wq, Wk, Wv, ln_n1_g, ln_n1_b);

    dim3 grid2(NN, BB);
    k_edge<<<grid2, 256, EDGE_SMEM_BYTES>>>(e, We, Wg, ln_e1_g, ln_e1_b);

    dim3 grid3(4*NN, BB);
    k_edge_finish_mlp<<<grid3, 256, K3_SMEM_BYTES>>>(e, Wo_e,
                                                     ln_e1_g, ln_e1_b,
                                                     ln_e2_g, ln_e2_b,
                                                     me_w1, me_b1, me_w2, me_b2,
                                                     e_out);

    k_node_finish<<<BB*NN, 64>>>(Wo_n, ln_n2_g, ln_n2_b,
                                 mn_w1, mn_b1, mn_w2, mn_b2, n_out);
}

// round 11
// speedup vs baseline: 2.8582x; 1.5729x over previous
#include <cuda_runtime.h>
#include <math.h>
#include <stdint.h>

#define BB 2
#define NN 512
#define DD 64
#define HH 8
#define DHH 128

// ----------------- k_edge smem layout (floats) -----------------
#define OFF_ELOG   0        // 8*520 = 4160
#define OFF_WEP    4160     // 512  (g1-scaled We)
#define OFF_WGP    4672     // 512  (g1-scaled Wg)
#define OFF_Q      5184     // 64
#define OFF_SE     5248     // 8
#define OFF_CE     5256     // 8
#define OFF_SG     5264     // 8
#define OFF_CG     5272     // 8
#define OFF_CENT   5280     // 8
#define OFF_WPART  5288     // 64
#define OFF_ET     5352     // 128 x 68 staged e tile   (8704)
#define OFF_KT     14056    // 128 x 68 staged K tile   (8704)
#define EDGE_SMEM_FLOATS 22760
#define EDGE_SMEM_BYTES  (EDGE_SMEM_FLOATS*4)   // 91040 B

// ----------------- K3 (finish + mlp) smem layout (floats) -----------------
#define KA_OFF    0          // sA   128 x 68 fp32 (8704)
#define KW1_OFF   8704       // sW1  64 x 136 tf32
#define KH_OFF    17408      // sH   128 x 132 tf32
#define KW2_OFF   34304      // sW2  128 x 72 tf32
#define KB1_OFF   43520      // 128
#define KB2_OFF   43648      // 64
#define KWOE_OFF  43712      // 512  (Wo_e [8][64])
#define KEL_OFF   44224      // 1024 (Elog slice [8][128])
#define KG1_OFF   45248      // 64
#define KBE1_OFF  45312      // 64
#define KG2_OFF   45376      // 64
#define KBE2_OFF  45440      // 64
#define K3_SMEM_FLOATS 45504
#define K3_SMEM_BYTES  (K3_SMEM_FLOATS*4)   // 182016 B

__device__ __align__(16) float g_n1[BB*NN*DD];
__device__ __align__(16) float g_q [BB*NN*DD];
__device__ __align__(16) float g_k [BB*NN*DD];
__device__ __align__(16) float g_v [BB*NN*DD];
__device__ __align__(16) float g_vc[BB*NN*DD];
__device__ __align__(16) float g_elog[(size_t)BB*HH*NN*NN];   // 16.8 MB

__device__ __forceinline__ uint32_t f2tf32(float x) {
    uint32_t r;
    asm("cvt.rna.tf32.f32 %0, %1;" : "=r"(r) : "f"(x));
    return r;
}

__device__ __forceinline__ void mma_tf32(float& c0, float& c1, float& c2, float& c3,
                                         uint32_t a0, uint32_t a1,
                                         uint32_t a2, uint32_t a3,
                                         uint32_t b0, uint32_t b1) {
    asm volatile(
        "mma.sync.aligned.m16n8k8.row.col.f32.tf32.tf32.f32 "
        "{%0,%1,%2,%3},{%4,%5,%6,%7},{%8,%9},{%0,%1,%2,%3};"
        : "+f"(c0), "+f"(c1), "+f"(c2), "+f"(c3)
        : "r"(a0), "r"(a1), "r"(a2), "r"(a3), "r"(b0), "r"(b1));
}

// ---------------------------------------------------------------------------
// K1: node LN + Q/K/V projection.
// ---------------------------------------------------------------------------
__global__ void k_node_prep(const float* __restrict__ n,
                            const float* __restrict__ Wq,
                            const float* __restrict__ Wk,
                            const float* __restrict__ Wv,
                            const float* __restrict__ lng,
                            const float* __restrict__ lnb)
{
    int row = blockIdx.x;
    int o = threadIdx.x;
    __shared__ float sx[DD];
    __shared__ float sn1[DD];
    sx[o] = n[row*DD + o];
    __syncthreads();
    float s = 0.f;
    #pragma unroll
    for (int k = 0; k < DD; k++) s += sx[k];
    float m = s * (1.f/DD);
    float v = 0.f;
    #pragma unroll
    for (int k = 0; k < DD; k++) { float d = sx[k]-m; v += d*d; }
    v *= (1.f/DD);
    float rstd = rsqrtf(v + 1e-5f);
    float n1 = (sx[o]-m)*rstd*lng[o] + lnb[o];
    sn1[o] = n1;
    g_n1[row*DD + o] = n1;
    __syncthreads();
    float q = 0.f, kk = 0.f, vv = 0.f;
    #pragma unroll
    for (int k = 0; k < DD; k++) {
        float a = sn1[k];
        q  += a * Wq[k*DD + o];
        kk += a * Wk[k*DD + o];
        vv += a * Wv[k*DD + o];
    }
    g_q[row*DD + o] = q;
    g_k[row*DD + o] = kk;
    g_v[row*DD + o] = vv;
}

// ---------------------------------------------------------------------------
// K2: edge attention, smem-staged coalesced chunks. Lane pair per j-row.
// Writes Elog to g_elog (coalesced at end) and vc to g_vc. grid=(N,B), 256 thr.
// ---------------------------------------------------------------------------
__global__ void __launch_bounds__(256, 1)
k_edge(const float* __restrict__ e,
       const float* __restrict__ We, const float* __restrict__ Wg,
       const float* __restrict__ lg1, const float* __restrict__ lb1)
{
    extern __shared__ float sm[];
    float* sElog  = sm + OFF_ELOG;
    float* sWeP   = sm + OFF_WEP;
    float* sWgP   = sm + OFF_WGP;
    float* sQ     = sm + OFF_Q;
    float* sSe    = sm + OFF_SE;
    float* sCe    = sm + OFF_CE;
    float* sSg    = sm + OFF_SG;
    float* sCg    = sm + OFF_CG;
    float* sCent  = sm + OFF_CENT;
    float* sWpart = sm + OFF_WPART;
    float* sE     = sm + OFF_ET;
    float* sK     = sm + OFF_KT;

    const int i    = blockIdx.x;
    const int b    = blockIdx.y;
    const int tid  = threadIdx.x;
    const int lane = tid & 31;
    const int warp = tid >> 5;
    const int rowbn = b*NN + i;

    const int r    = tid >> 1;        // j-row within chunk (0..127)
    const int half = tid & 1;         // which 32-dim half of k
    const int k0w  = half * 32;

    for (int t = tid; t < 512; t += 256) {
        int k = t >> 3;
        float g = lg1[k];
        sWeP[t] = g * We[t];
        sWgP[t] = g * Wg[t];
    }
    if (tid < 64) sQ[tid] = g_q[rowbn*DD + tid];
    __syncthreads();
    if (tid < 8) {
        float se=0.f, ce=0.f, sg=0.f, cg=0.f;
        for (int k = 0; k < 64; k++) {
            float bb = lb1[k];
            se += sWeP[k*8 + tid];
            sg += sWgP[k*8 + tid];
            ce += bb * We[k*8 + tid];
            cg += bb * Wg[k*8 + tid];
        }
        sSe[tid]=se; sCe[tid]=ce; sSg[tid]=sg; sCg[tid]=cg;
    }

    const float scale = 0.35355339059327373f;
    float gacc[HH];
    #pragma unroll
    for (int h = 0; h < HH; h++) gacc[h] = 0.f;

    for (int ch = 0; ch < 4; ch++) {
        const int j0 = ch*128;
        __syncthreads();   // previous chunk consumers done / params ready
        // ---- coalesced staging of e and K chunks ----
        for (int t = tid; t < 2048; t += 256) {
            int row = t >> 4, q = t & 15;
            *(float4*)(sE + row*68 + q*4) =
                *(const float4*)(e + ((size_t)rowbn*NN + j0 + row)*DD + q*4);
            *(float4*)(sK + row*68 + q*4) =
                *(const float4*)(g_k + ((size_t)b*NN + j0 + row)*DD + q*4);
        }
        __syncthreads();

        // ---- compute: lane pair handles row r, this lane does k half ----
        float s = 0.f, sq = 0.f;
        float Eh[HH], Gh[HH];
        #pragma unroll
        for (int h = 0; h < HH; h++) { Eh[h]=0.f; Gh[h]=0.f; }
        float ac0=0.f, ac1=0.f, ac2=0.f, ac3=0.f;

        const float4* xp = (const float4*)(sE + r*68 + k0w);
        const float4* kp = (const float4*)(sK + r*68 + k0w);
        const float4* qp = (const float4*)(sQ + k0w);

        #pragma unroll
        for (int q = 0; q < 8; q++) {
            float4 xv = xp[q];
            float4 kv = kp[q];
            float4 qv = qp[q];
            s  += (xv.x + xv.y) + (xv.z + xv.w);
            sq += (xv.x*xv.x + xv.y*xv.y) + (xv.z*xv.z + xv.w*xv.w);
            float dot = qv.x*kv.x + qv.y*kv.y + qv.z*kv.z + qv.w*kv.w;
            if (q < 2)      ac0 += dot;
            else if (q < 4) ac1 += dot;
            else if (q < 6) ac2 += dot;
            else            ac3 += dot;
            float xs[4] = {xv.x, xv.y, xv.z, xv.w};
            #pragma unroll
            for (int c = 0; c < 4; c++) {
                int k = k0w + q*4 + c;
                float xk = xs[c];
                const float4* we = (const float4*)(sWeP + k*8);
                const float4* wg = (const float4*)(sWgP + k*8);
                float4 a0 = we[0], a1 = we[1];
                float4 c0 = wg[0], c1 = wg[1];
                Eh[0]+=xk*a0.x; Eh[1]+=xk*a0.y; Eh[2]+=xk*a0.z; Eh[3]+=xk*a0.w;
                Eh[4]+=xk*a1.x; Eh[5]+=xk*a1.y; Eh[6]+=xk*a1.z; Eh[7]+=xk*a1.w;
                Gh[0]+=xk*c0.x; Gh[1]+=xk*c0.y; Gh[2]+=xk*c0.z; Gh[3]+=xk*c0.w;
                Gh[4]+=xk*c1.x; Gh[5]+=xk*c1.y; Gh[6]+=xk*c1.z; Gh[7]+=xk*c1.w;
            }
        }

        // combine halves (partner = lane^1)
        s  += __shfl_xor_sync(0xffffffffu, s, 1);
        sq += __shfl_xor_sync(0xffffffffu, sq, 1);
        #pragma unroll
        for (int h = 0; h < HH; h++) {
            Eh[h] += __shfl_xor_sync(0xffffffffu, Eh[h], 1);
            Gh[h] += __shfl_xor_sync(0xffffffffu, Gh[h], 1);
        }
        // q.k head exchange: half 0 owns heads 0..3, half 1 owns heads 4..7
        float p0 = __shfl_xor_sync(0xffffffffu, ac0, 1);
        float p1 = __shfl_xor_sync(0xffffffffu, ac1, 1);
        float p2 = __shfl_xor_sync(0xffffffffu, ac2, 1);
        float p3 = __shfl_xor_sync(0xffffffffu, ac3, 1);
        float qk0 = half ? p0 : ac0;
        float qk1 = half ? p1 : ac1;
        float qk2 = half ? p2 : ac2;
        float qk3 = half ? p3 : ac3;
        float qk4 = half ? ac0 : p0;
        float qk5 = half ? ac1 : p1;
        float qk6 = half ? ac2 : p2;
        float qk7 = half ? ac3 : p3;

        float m = s * (1.f/64.f);
        float var = sq * (1.f/64.f) - m*m;
        float rstd = rsqrtf(var + 1e-5f);

        if (half == 0) {
            const int j = j0 + r;
            float qks[8] = {qk0,qk1,qk2,qk3,qk4,qk5,qk6,qk7};
            #pragma unroll
            for (int h = 0; h < HH; h++) {
                float E = rstd*(Eh[h] - m*sSe[h]) + sCe[h];
                float G = rstd*(Gh[h] - m*sSg[h]) + sCg[h];
                float a = fminf(fmaxf(qks[h]*scale, -5.f), 5.f);
                sElog[h*520 + j] = a + E;
                gacc[h] += 1.f/(1.f + expf(-G));
            }
        }
    }

    // gate-sum reduction -> centrality (odd lanes contribute 0)
    #pragma unroll
    for (int h = 0; h < HH; h++) {
        #pragma unroll
        for (int off = 16; off > 0; off >>= 1)
            gacc[h] += __shfl_xor_sync(0xffffffffu, gacc[h], off);
    }
    if (lane == 0) {
        #pragma unroll
        for (int h = 0; h < HH; h++) sWpart[warp*8 + h] = gacc[h];
    }
    __syncthreads();
    if (tid < 8) {
        float ssum = 0.f;
        #pragma unroll
        for (int w = 0; w < 8; w++) ssum += sWpart[w*8 + tid];
        sCent[tid] = log1pf(ssum);
    }
    __syncthreads();

    // softmax + P@V (warp per head)
    {
        const int h = warp;
        const float* el = sElog + h*520;
        float mmax = -1e30f;
        for (int j = lane; j < NN; j += 32) mmax = fmaxf(mmax, el[j]);
        #pragma unroll
        for (int off = 16; off > 0; off >>= 1)
            mmax = fmaxf(mmax, __shfl_xor_sync(0xffffffffu, mmax, off));

        float denom = 0.f;
        float p0=0,p1=0,p2=0,p3=0,p4=0,p5=0,p6=0,p7=0;
        for (int j = lane; j < NN; j += 32) {
            float t = expf(el[j] - mmax);
            denom += t;
            const float4* vp = (const float4*)(g_v + (b*NN + j)*DD + h*8);
            float4 va = vp[0], vb = vp[1];
            p0 += t*va.x; p1 += t*va.y; p2 += t*va.z; p3 += t*va.w;
            p4 += t*vb.x; p5 += t*vb.y; p6 += t*vb.z; p7 += t*vb.w;
        }
        #pragma unroll
        for (int off = 16; off > 0; off >>= 1) {
            denom += __shfl_xor_sync(0xffffffffu, denom, off);
            p0 += __shfl_xor_sync(0xffffffffu, p0, off);
            p1 += __shfl_xor_sync(0xffffffffu, p1, off);
            p2 += __shfl_xor_sync(0xffffffffu, p2, off);
            p3 += __shfl_xor_sync(0xffffffffu, p3, off);
            p4 += __shfl_xor_sync(0xffffffffu, p4, off);
            p5 += __shfl_xor_sync(0xffffffffu, p5, off);
            p6 += __shfl_xor_sync(0xffffffffu, p6, off);
            p7 += __shfl_xor_sync(0xffffffffu, p7, off);
        }
        if (lane == 0) {
            float c = sCent[h] / denom;
            float* dst = g_vc + rowbn*DD + h*8;
            dst[0]=p0*c; dst[1]=p1*c; dst[2]=p2*c; dst[3]=p3*c;
            dst[4]=p4*c; dst[5]=p5*c; dst[6]=p6*c; dst[7]=p7*c;
        }
    }

    // coalesced Elog writeback
    __syncthreads();
    for (int t = tid; t < HH*NN; t += 256) {
        int h = t >> 9, j = t & 511;
        g_elog[(((size_t)b*HH + h)*NN + i)*NN + j] = sElog[h*520 + j];
    }
}

// ---------------------------------------------------------------------------
// K3: fused edge finish + MLP (unchanged from R10).
// ---------------------------------------------------------------------------
__global__ void __launch_bounds__(256, 1)
k_edge_finish_mlp(const float* __restrict__ e,
                  const float* __restrict__ WoE,
                  const float* __restrict__ lg1, const float* __restrict__ lb1,
                  const float* __restrict__ lg2, const float* __restrict__ lb2,
                  const float* __restrict__ W1, const float* __restrict__ b1,
                  const float* __restrict__ W2, const float* __restrict__ b2,
                  float* __restrict__ e_out)
{
    extern __shared__ float sm[];
    float*    sA   = sm + KA_OFF;
    uint32_t* sW1  = (uint32_t*)(sm + KW1_OFF);
    uint32_t* sH   = (uint32_t*)(sm + KH_OFF);
    uint32_t* sW2  = (uint32_t*)(sm + KW2_OFF);
    float*    sB1  = sm + KB1_OFF;
    float*    sB2  = sm + KB2_OFF;
    float*    sWoe = sm + KWOE_OFF;
    float*    sEl  = sm + KEL_OFF;
    float*    sG1  = sm + KG1_OFF;
    float*    sBe1 = sm + KBE1_OFF;
    float*    sG2  = sm + KG2_OFF;
    float*    sBe2 = sm + KBE2_OFF;

    const int tid  = threadIdx.x;
    const int lane = tid & 31;
    const int warp = tid >> 5;
    const int gid  = lane >> 2;
    const int tig  = lane & 3;

    const int bx = blockIdx.x;
    const int jc = bx & 3;
    const int i  = bx >> 2;
    const int b  = blockIdx.y;
    const int rowbn = b*NN + i;
    const size_t gj0 = (size_t)rowbn*NN + jc*128;

    for (int t = tid; t < 64*DHH; t += 256) {
        int k = t >> 7, u = t & 127;
        sW1[k*136 + u] = f2tf32(W1[t]);
    }
    for (int t = tid; t < DHH*64; t += 256) {
        int u = t >> 6, c = t & 63;
        sW2[u*72 + c] = f2tf32(W2[t]);
    }
    for (int t = tid; t < 512; t += 256) sWoe[t] = WoE[t];
    if (tid < 128) sB1[tid] = b1[tid];
    if (tid < 64) {
        sB2[tid]  = b2[tid];
        sG1[tid]  = lg1[tid]; sBe1[tid] = lb1[tid];
        sG2[tid]  = lg2[tid]; sBe2[tid] = lb2[tid];
    }
    for (int t = tid; t < 1024; t += 256) {
        int h = t >> 7, jl = t & 127;
        sEl[h*128 + jl] = g_elog[(((size_t)b*HH + h)*NN + i)*NN + jc*128 + jl];
    }
    for (int t = tid; t < 128*16; t += 256) {
        int row = t >> 4, q = t & 15;
        float4 v = *(const float4*)(e + (gj0 + row)*DD + q*4);
        *(float4*)(sA + row*68 + q*4) = v;
    }
    __syncthreads();

    // phase A: e3 = LN2( LN1(x) + El @ WoE ) in sA
    {
        const int r    = tid >> 1;
        const int halfc = tid & 1;
        const int c0   = halfc*32;

        float s = 0.f, sq = 0.f;
        #pragma unroll
        for (int c = 0; c < 32; c++) {
            float v = sA[r*68 + c0 + c];
            s += v; sq += v*v;
        }
        s  += __shfl_xor_sync(0xffffffffu, s, 1);
        sq += __shfl_xor_sync(0xffffffffu, sq, 1);
        float m = s*(1.f/64.f);
        float rstd = rsqrtf(sq*(1.f/64.f) - m*m + 1e-5f);

        float el0=sEl[r], el1=sEl[128+r], el2=sEl[256+r], el3=sEl[384+r];
        float el4=sEl[512+r], el5=sEl[640+r], el6=sEl[768+r], el7=sEl[896+r];

        float y[32];
        #pragma unroll
        for (int c = 0; c < 32; c++) {
            int k = c0 + c;
            float x = sA[r*68 + k];
            float a = (x - m)*rstd*sG1[k] + sBe1[k];
            a += el0*sWoe[k]       + el1*sWoe[64 + k]
               + el2*sWoe[128 + k] + el3*sWoe[192 + k]
               + el4*sWoe[256 + k] + el5*sWoe[320 + k]
               + el6*sWoe[384 + k] + el7*sWoe[448 + k];
            y[c] = a;
        }
        float s2 = 0.f, q2 = 0.f;
        #pragma unroll
        for (int c = 0; c < 32; c++) { s2 += y[c]; q2 += y[c]*y[c]; }
        s2 += __shfl_xor_sync(0xffffffffu, s2, 1);
        q2 += __shfl_xor_sync(0xffffffffu, q2, 1);
        float m2 = s2*(1.f/64.f);
        float rstd2 = rsqrtf(q2*(1.f/64.f) - m2*m2 + 1e-5f);
        #pragma unroll
        for (int c = 0; c < 32; c++) {
            int k = c0 + c;
            sA[r*68 + k] = (y[c] - m2)*rstd2*sG2[k] + sBe2[k];
        }
    }
    __syncthreads();

    // phase B: tf32 mma MLP
    const int row0 = warp*16 + gid;
    const int row1 = row0 + 8;

    uint32_t af0[8], af1[8], af2[8], af3[8];
    #pragma unroll
    for (int kt = 0; kt < 8; kt++) {
        int c0 = kt*8 + tig;
        af0[kt] = f2tf32(sA[row0*68 + c0]);
        af1[kt] = f2tf32(sA[row1*68 + c0]);
        af2[kt] = f2tf32(sA[row0*68 + c0 + 4]);
        af3[kt] = f2tf32(sA[row1*68 + c0 + 4]);
    }

    #pragma unroll
    for (int nc = 0; nc < 4; nc++) {
        float a00=0,a01=0,a02=0,a03=0;
        float a10=0,a11=0,a12=0,a13=0;
        float a20=0,a21=0,a22=0,a23=0;
        float a30=0,a31=0,a32=0,a33=0;
        #pragma unroll
        for (int kt = 0; kt < 8; kt++) {
            const uint32_t* w = sW1 + (kt*8 + tig)*136 + nc*32 + gid;
            uint32_t b00 = w[0],    b01 = w[4*136];
            uint32_t b10 = w[8],    b11 = w[4*136 + 8];
            uint32_t b20 = w[16],   b21 = w[4*136 + 16];
            uint32_t b30 = w[24],   b31 = w[4*136 + 24];
            mma_tf32(a00,a01,a02,a03, af0[kt],af1[kt],af2[kt],af3[kt], b00,b01);
            mma_tf32(a10,a11,a12,a13, af0[kt],af1[kt],af2[kt],af3[kt], b10,b11);
            mma_tf32(a20,a21,a22,a23, af0[kt],af1[kt],af2[kt],af3[kt], b20,b21);
            mma_tf32(a30,a31,a32,a33, af0[kt],af1[kt],af2[kt],af3[kt], b30,b31);
        }
        #pragma unroll
        for (int nt = 0; nt < 4; nt++) {
            float c0v, c1v, c2v, c3v;
            if (nt == 0)      { c0v=a00; c1v=a01; c2v=a02; c3v=a03; }
            else if (nt == 1) { c0v=a10; c1v=a11; c2v=a12; c3v=a13; }
            else if (nt == 2) { c0v=a20; c1v=a21; c2v=a22; c3v=a23; }
            else              { c0v=a30; c1v=a31; c2v=a32; c3v=a33; }
            int c = nc*32 + nt*8 + 2*tig;
            float bb0 = sB1[c], bb1 = sB1[c+1];
            sH[row0*132 + c    ] = f2tf32(fmaxf(c0v + bb0, 0.f));
            sH[row0*132 + c + 1] = f2tf32(fmaxf(c1v + bb1, 0.f));
            sH[row1*132 + c    ] = f2tf32(fmaxf(c2v + bb0, 0.f));
            sH[row1*132 + c + 1] = f2tf32(fmaxf(c3v + bb1, 0.f));
        }
    }
    __syncwarp();

    #pragma unroll
    for (int nc = 0; nc < 2; nc++) {
        float a00=0,a01=0,a02=0,a03=0;
        float a10=0,a11=0,a12=0,a13=0;
        float a20=0,a21=0,a22=0,a23=0;
        float a30=0,a31=0,a32=0,a33=0;
        #pragma unroll
        for (int kt = 0; kt < 16; kt++) {
            int c0 = kt*8 + tig;
            uint32_t h0 = sH[row0*132 + c0];
            uint32_t h1 = sH[row1*132 + c0];
            uint32_t h2 = sH[row0*132 + c0 + 4];
            uint32_t h3 = sH[row1*132 + c0 + 4];
            const uint32_t* w = sW2 + c0*72 + nc*32 + gid;
            uint32_t b00 = w[0],  b01 = w[4*72];
            uint32_t b10 = w[8],  b11 = w[4*72 + 8];
            uint32_t b20 = w[16], b21 = w[4*72 + 16];
            uint32_t b30 = w[24], b31 = w[4*72 + 24];
            mma_tf32(a00,a01,a02,a03, h0,h1,h2,h3, b00,b01);
            mma_tf32(a10,a11,a12,a13, h0,h1,h2,h3, b10,b11);
            mma_tf32(a20,a21,a22,a23, h0,h1,h2,h3, b20,b21);
            mma_tf32(a30,a31,a32,a33, h0,h1,h2,h3, b30,b31);
        }
        #pragma unroll
        for (int nt = 0; nt < 4; nt++) {
            float c0v, c1v, c2v, c3v;
            if (nt == 0)      { c0v=a00; c1v=a01; c2v=a02; c3v=a03; }
            else if (nt == 1) { c0v=a10; c1v=a11; c2v=a12; c3v=a13; }
            else if (nt == 2) { c0v=a20; c1v=a21; c2v=a22; c3v=a23; }
            else              { c0v=a30; c1v=a31; c2v=a32; c3v=a33; }
            int c = nc*32 + nt*8 + 2*tig;
            float b20v = sB2[c], b21v = sB2[c+1];
            float r00 = sA[row0*68 + c    ] + fmaxf(c0v + b20v, 0.f);
            float r01 = sA[row0*68 + c + 1] + fmaxf(c1v + b21v, 0.f);
            float r10 = sA[row1*68 + c    ] + fmaxf(c2v + b20v, 0.f);
            float r11 = sA[row1*68 + c + 1] + fmaxf(c3v + b21v, 0.f);
            *(float2*)(e_out + (gj0 + row0)*DD + c) = make_float2(r00, r01);
            *(float2*)(e_out + (gj0 + row1)*DD + c) = make_float2(r10, r11);
        }
    }
}

// ---------------------------------------------------------------------------
// K4: node finish.
// ---------------------------------------------------------------------------
__global__ void k_node_finish(const float* __restrict__ Wo_n,
                              const float* __restrict__ lng,
                              const float* __restrict__ lnb,
                              const float* __restrict__ W1,
                              const float* __restrict__ Bi1,
                              const float* __restrict__ W2,
                              const float* __restrict__ Bi2,
                              float* __restrict__ n_out)
{
    int row = blockIdx.x;
    int o = threadIdx.x;
    __shared__ float svc[DD];
    __shared__ float sn2[DD];
    __shared__ float sn3[DD];
    __shared__ float sh[DHH];
    svc[o] = g_vc[row*DD + o];
    __syncthreads();
    float acc = 0.f;
    #pragma unroll
    for (int k = 0; k < DD; k++) acc += svc[k]*Wo_n[k*DD + o];
    float n2 = g_n1[row*DD + o] + acc;
    sn2[o] = n2;
    __syncthreads();
    float s = 0.f;
    #pragma unroll
    for (int k = 0; k < DD; k++) s += sn2[k];
    float m = s*(1.f/DD);
    float v = 0.f;
    #pragma unroll
    for (int k = 0; k < DD; k++) { float d = sn2[k]-m; v += d*d; }
    v *= (1.f/DD);
    float rstd = rsqrtf(v + 1e-5f);
    float n3 = (n2-m)*rstd*lng[o] + lnb[o];
    sn3[o] = n3;
    __syncthreads();
    #pragma unroll
    for (int uu = 0; uu < 2; uu++) {
        int u = o + uu*64;
        float h = Bi1[u];
        #pragma unroll
        for (int k = 0; k < DD; k++) h += sn3[k]*W1[k*DHH + u];
        sh[u] = fmaxf(h, 0.f);
    }
    __syncthreads();
    float oacc = Bi2[o];
    #pragma unroll
    for (int u = 0; u < DHH; u++) oacc += sh[u]*W2[u*DD + o];
    n_out[row*DD + o] = n3 + fmaxf(oacc, 0.f);
}

extern "C" void kernel_launch(void* const* d_in, const int* in_sizes, int n_in,
                              void* d_out, int out_size)
{
    const float* n       = (const float*)d_in[0];
    const float* e       = (const float*)d_in[1];
    const float* Wq      = (const float*)d_in[2];
    const float* Wk      = (const float*)d_in[3];
    const float* Wv      = (const float*)d_in[4];
    const float* Wo_n    = (const float*)d_in[5];
    const float* We      = (const float*)d_in[6];
    const float* Wg      = (const float*)d_in[7];
    const float* Wo_e    = (const float*)d_in[8];
    const float* ln_n1_g = (const float*)d_in[9];
    const float* ln_n1_b = (const float*)d_in[10];
    const float* ln_e1_g = (const float*)d_in[11];
    const float* ln_e1_b = (const float*)d_in[12];
    const float* ln_n2_g = (const float*)d_in[13];
    const float* ln_n2_b = (const float*)d_in[14];
    const float* ln_e2_g = (const float*)d_in[15];
    const float* ln_e2_b = (const float*)d_in[16];
    const float* mn_w1   = (const float*)d_in[17];
    const float* mn_b1   = (const float*)d_in[18];
    const float* mn_w2   = (const float*)d_in[19];
    const float* mn_b2   = (const float*)d_in[20];
    const float* me_w1   = (const float*)d_in[21];
    const float* me_b1   = (const float*)d_in[22];
    const float* me_w2   = (const float*)d_in[23];
    const float* me_b2   = (const float*)d_in[24];

    float* out   = (float*)d_out;
    float* n_out = out;
    float* e_out = out + BB*NN*DD;

    cudaFuncSetAttribute(k_edge, cudaFuncAttributeMaxDynamicSharedMemorySize, EDGE_SMEM_BYTES);
    cudaFuncSetAttribute(k_edge_finish_mlp, cudaFuncAttributeMaxDynamicSharedMemorySize, K3_SMEM_BYTES);

    k_node_prep<<<BB*NN, 64>>>(n, Wq, Wk, Wv, ln_n1_g, ln_n1_b);

    dim3 grid2(NN, BB);
    k_edge<<<grid2, 256, EDGE_SMEM_BYTES>>>(e, We, Wg, ln_e1_g, ln_e1_b);

    dim3 grid3(4*NN, BB);
    k_edge_finish_mlp<<<grid3, 256, K3_SMEM_BYTES>>>(e, Wo_e,
                                                     ln_e1_g, ln_e1_b,
                                                     ln_e2_g, ln_e2_b,
                                                     me_w1, me_b1, me_w2, me_b2,
                                                     e_out);

    k_node_finish<<<BB*NN, 64>>>(Wo_n, ln_n2_g, ln_n2_b,
                                 mn_w1, mn_b1, mn_w2, mn_b2, n_out);
}

// round 12
// speedup vs baseline: 2.9791x; 1.0423x over previous
#include <cuda_runtime.h>
#include <math.h>
#include <stdint.h>

#define BB 2
#define NN 512
#define DD 64
#define HH 8
#define DHH 128

// ----------------- k_edge smem layout (floats) -----------------
#define OFF_ELOG   0        // 8*520 = 4160
#define OFF_WEP    4160     // 512  (g1-scaled We)
#define OFF_WGP    4672     // 512  (g1-scaled Wg)
#define OFF_Q      5184     // 64
#define OFF_SE     5248     // 8
#define OFF_CE     5256     // 8
#define OFF_SG     5264     // 8
#define OFF_CG     5272     // 8
#define OFF_CENT   5280     // 8
#define OFF_WPART  5288     // 64
#define OFF_ET     5352     // 128 x 68 staged e tile   (8704)
#define OFF_KT     14056    // 128 x 68 staged K tile   (8704)
#define EDGE_SMEM_FLOATS 22760
#define EDGE_SMEM_BYTES  (EDGE_SMEM_FLOATS*4)   // 91040 B

// ----------------- K3 (finish + mlp) smem layout (floats) -----------------
#define KA_OFF    0          // sA   128 x 68 fp32 (8704)
#define KW1_OFF   8704       // sW1  64 x 136 tf32
#define KH_OFF    17408      // sH   128 x 132 tf32
#define KW2_OFF   34304      // sW2  128 x 72 tf32
#define KB1_OFF   43520      // 128
#define KB2_OFF   43648      // 64
#define KWOE_OFF  43712      // 512  (Wo_e [8][64])
#define KEL_OFF   44224      // 1024 (Elog slice [8][128])
#define KG1_OFF   45248      // 64
#define KBE1_OFF  45312      // 64
#define KG2_OFF   45376      // 64
#define KBE2_OFF  45440      // 64
#define K3_SMEM_FLOATS 45504
#define K3_SMEM_BYTES  (K3_SMEM_FLOATS*4)   // 182016 B

__device__ __align__(16) float g_n1[BB*NN*DD];
__device__ __align__(16) float g_q [BB*NN*DD];
__device__ __align__(16) float g_k [BB*NN*DD];
__device__ __align__(16) float g_vt[BB*HH*8*NN];   // V transposed: [b][h][d][j]
__device__ __align__(16) float g_vc[BB*NN*DD];
__device__ __align__(16) float g_elog[(size_t)BB*HH*NN*NN];   // 16.8 MB

__device__ __forceinline__ uint32_t f2tf32(float x) {
    uint32_t r;
    asm("cvt.rna.tf32.f32 %0, %1;" : "=r"(r) : "f"(x));
    return r;
}

__device__ __forceinline__ void mma_tf32(float& c0, float& c1, float& c2, float& c3,
                                         uint32_t a0, uint32_t a1,
                                         uint32_t a2, uint32_t a3,
                                         uint32_t b0, uint32_t b1) {
    asm volatile(
        "mma.sync.aligned.m16n8k8.row.col.f32.tf32.tf32.f32 "
        "{%0,%1,%2,%3},{%4,%5,%6,%7},{%8,%9},{%0,%1,%2,%3};"
        : "+f"(c0), "+f"(c1), "+f"(c2), "+f"(c3)
        : "r"(a0), "r"(a1), "r"(a2), "r"(a3), "r"(b0), "r"(b1));
}

// ---------------------------------------------------------------------------
// K1: node LN + Q/K/V projection (V also stored transposed).
// ---------------------------------------------------------------------------
__global__ void k_node_prep(const float* __restrict__ n,
                            const float* __restrict__ Wq,
                            const float* __restrict__ Wk,
                            const float* __restrict__ Wv,
                            const float* __restrict__ lng,
                            const float* __restrict__ lnb)
{
    int row = blockIdx.x;
    int o = threadIdx.x;
    __shared__ float sx[DD];
    __shared__ float sn1[DD];
    sx[o] = n[row*DD + o];
    __syncthreads();
    float s = 0.f;
    #pragma unroll
    for (int k = 0; k < DD; k++) s += sx[k];
    float m = s * (1.f/DD);
    float v = 0.f;
    #pragma unroll
    for (int k = 0; k < DD; k++) { float d = sx[k]-m; v += d*d; }
    v *= (1.f/DD);
    float rstd = rsqrtf(v + 1e-5f);
    float n1 = (sx[o]-m)*rstd*lng[o] + lnb[o];
    sn1[o] = n1;
    g_n1[row*DD + o] = n1;
    __syncthreads();
    float q = 0.f, kk = 0.f, vv = 0.f;
    #pragma unroll
    for (int k = 0; k < DD; k++) {
        float a = sn1[k];
        q  += a * Wq[k*DD + o];
        kk += a * Wk[k*DD + o];
        vv += a * Wv[k*DD + o];
    }
    g_q[row*DD + o] = q;
    g_k[row*DD + o] = kk;
    // transposed V: [b][h][d][j]
    int b = row >> 9;          // row / NN
    int j = row & 511;         // row % NN
    int h = o >> 3;
    int d = o & 7;
    g_vt[((b*HH + h)*8 + d)*NN + j] = vv;
}

// ---------------------------------------------------------------------------
// K2: edge attention, smem-staged coalesced chunks. Lane pair per j-row.
// ---------------------------------------------------------------------------
__global__ void __launch_bounds__(256, 1)
k_edge(const float* __restrict__ e,
       const float* __restrict__ We, const float* __restrict__ Wg,
       const float* __restrict__ lg1, const float* __restrict__ lb1)
{
    extern __shared__ float sm[];
    float* sElog  = sm + OFF_ELOG;
    float* sWeP   = sm + OFF_WEP;
    float* sWgP   = sm + OFF_WGP;
    float* sQ     = sm + OFF_Q;
    float* sSe    = sm + OFF_SE;
    float* sCe    = sm + OFF_CE;
    float* sSg    = sm + OFF_SG;
    float* sCg    = sm + OFF_CG;
    float* sCent  = sm + OFF_CENT;
    float* sWpart = sm + OFF_WPART;
    float* sE     = sm + OFF_ET;
    float* sK     = sm + OFF_KT;

    const int i    = blockIdx.x;
    const int b    = blockIdx.y;
    const int tid  = threadIdx.x;
    const int lane = tid & 31;
    const int warp = tid >> 5;
    const int rowbn = b*NN + i;

    const int r    = tid >> 1;
    const int half = tid & 1;
    const int k0w  = half * 32;

    for (int t = tid; t < 512; t += 256) {
        int k = t >> 3;
        float g = lg1[k];
        sWeP[t] = g * We[t];
        sWgP[t] = g * Wg[t];
    }
    if (tid < 64) sQ[tid] = g_q[rowbn*DD + tid];
    __syncthreads();
    if (tid < 8) {
        float se=0.f, ce=0.f, sg=0.f, cg=0.f;
        for (int k = 0; k < 64; k++) {
            float bb = lb1[k];
            se += sWeP[k*8 + tid];
            sg += sWgP[k*8 + tid];
            ce += bb * We[k*8 + tid];
            cg += bb * Wg[k*8 + tid];
        }
        sSe[tid]=se; sCe[tid]=ce; sSg[tid]=sg; sCg[tid]=cg;
    }

    const float scale = 0.35355339059327373f;
    float gacc[HH];
    #pragma unroll
    for (int h = 0; h < HH; h++) gacc[h] = 0.f;

    for (int ch = 0; ch < 4; ch++) {
        const int j0 = ch*128;
        __syncthreads();
        for (int t = tid; t < 2048; t += 256) {
            int row = t >> 4, q = t & 15;
            *(float4*)(sE + row*68 + q*4) =
                *(const float4*)(e + ((size_t)rowbn*NN + j0 + row)*DD + q*4);
            *(float4*)(sK + row*68 + q*4) =
                *(const float4*)(g_k + ((size_t)b*NN + j0 + row)*DD + q*4);
        }
        __syncthreads();

        float s = 0.f, sq = 0.f;
        float Eh[HH], Gh[HH];
        #pragma unroll
        for (int h = 0; h < HH; h++) { Eh[h]=0.f; Gh[h]=0.f; }
        float ac0=0.f, ac1=0.f, ac2=0.f, ac3=0.f;

        const float4* xp = (const float4*)(sE + r*68 + k0w);
        const float4* kp = (const float4*)(sK + r*68 + k0w);
        const float4* qp = (const float4*)(sQ + k0w);

        #pragma unroll
        for (int q = 0; q < 8; q++) {
            float4 xv = xp[q];
            float4 kv = kp[q];
            float4 qv = qp[q];
            s  += (xv.x + xv.y) + (xv.z + xv.w);
            sq += (xv.x*xv.x + xv.y*xv.y) + (xv.z*xv.z + xv.w*xv.w);
            float dot = qv.x*kv.x + qv.y*kv.y + qv.z*kv.z + qv.w*kv.w;
            if (q < 2)      ac0 += dot;
            else if (q < 4) ac1 += dot;
            else if (q < 6) ac2 += dot;
            else            ac3 += dot;
            float xs[4] = {xv.x, xv.y, xv.z, xv.w};
            #pragma unroll
            for (int c = 0; c < 4; c++) {
                int k = k0w + q*4 + c;
                float xk = xs[c];
                const float4* we = (const float4*)(sWeP + k*8);
                const float4* wg = (const float4*)(sWgP + k*8);
                float4 a0 = we[0], a1 = we[1];
                float4 c0 = wg[0], c1 = wg[1];
                Eh[0]+=xk*a0.x; Eh[1]+=xk*a0.y; Eh[2]+=xk*a0.z; Eh[3]+=xk*a0.w;
                Eh[4]+=xk*a1.x; Eh[5]+=xk*a1.y; Eh[6]+=xk*a1.z; Eh[7]+=xk*a1.w;
                Gh[0]+=xk*c0.x; Gh[1]+=xk*c0.y; Gh[2]+=xk*c0.z; Gh[3]+=xk*c0.w;
                Gh[4]+=xk*c1.x; Gh[5]+=xk*c1.y; Gh[6]+=xk*c1.z; Gh[7]+=xk*c1.w;
            }
        }

        s  += __shfl_xor_sync(0xffffffffu, s, 1);
        sq += __shfl_xor_sync(0xffffffffu, sq, 1);
        #pragma unroll
        for (int h = 0; h < HH; h++) {
            Eh[h] += __shfl_xor_sync(0xffffffffu, Eh[h], 1);
            Gh[h] += __shfl_xor_sync(0xffffffffu, Gh[h], 1);
        }
        float p0 = __shfl_xor_sync(0xffffffffu, ac0, 1);
        float p1 = __shfl_xor_sync(0xffffffffu, ac1, 1);
        float p2 = __shfl_xor_sync(0xffffffffu, ac2, 1);
        float p3 = __shfl_xor_sync(0xffffffffu, ac3, 1);
        float qk0 = half ? p0 : ac0;
        float qk1 = half ? p1 : ac1;
        float qk2 = half ? p2 : ac2;
        float qk3 = half ? p3 : ac3;
        float qk4 = half ? ac0 : p0;
        float qk5 = half ? ac1 : p1;
        float qk6 = half ? ac2 : p2;
        float qk7 = half ? ac3 : p3;

        float m = s * (1.f/64.f);
        float var = sq * (1.f/64.f) - m*m;
        float rstd = rsqrtf(var + 1e-5f);

        if (half == 0) {
            const int j = j0 + r;
            float qks[8] = {qk0,qk1,qk2,qk3,qk4,qk5,qk6,qk7};
            #pragma unroll
            for (int h = 0; h < HH; h++) {
                float E = rstd*(Eh[h] - m*sSe[h]) + sCe[h];
                float G = rstd*(Gh[h] - m*sSg[h]) + sCg[h];
                float a = fminf(fmaxf(qks[h]*scale, -5.f), 5.f);
                sElog[h*520 + j] = a + E;
                gacc[h] += 1.f/(1.f + expf(-G));
            }
        }
    }

    #pragma unroll
    for (int h = 0; h < HH; h++) {
        #pragma unroll
        for (int off = 16; off > 0; off >>= 1)
            gacc[h] += __shfl_xor_sync(0xffffffffu, gacc[h], off);
    }
    if (lane == 0) {
        #pragma unroll
        for (int h = 0; h < HH; h++) sWpart[warp*8 + h] = gacc[h];
    }
    __syncthreads();
    if (tid < 8) {
        float ssum = 0.f;
        #pragma unroll
        for (int w = 0; w < 8; w++) ssum += sWpart[w*8 + tid];
        sCent[tid] = log1pf(ssum);
    }
    __syncthreads();

    // softmax + P@V (warp per head), transposed V -> coalesced loads
    {
        const int h = warp;
        const float* el = sElog + h*520;
        const float* vt = g_vt + (size_t)(b*HH + h)*8*NN;
        float mmax = -1e30f;
        for (int j = lane; j < NN; j += 32) mmax = fmaxf(mmax, el[j]);
        #pragma unroll
        for (int off = 16; off > 0; off >>= 1)
            mmax = fmaxf(mmax, __shfl_xor_sync(0xffffffffu, mmax, off));

        float denom = 0.f;
        float p0=0,p1=0,p2=0,p3=0,p4=0,p5=0,p6=0,p7=0;
        for (int j = lane; j < NN; j += 32) {
            float t = expf(el[j] - mmax);
            denom += t;
            p0 += t*vt[0*NN + j];
            p1 += t*vt[1*NN + j];
            p2 += t*vt[2*NN + j];
            p3 += t*vt[3*NN + j];
            p4 += t*vt[4*NN + j];
            p5 += t*vt[5*NN + j];
            p6 += t*vt[6*NN + j];
            p7 += t*vt[7*NN + j];
        }
        #pragma unroll
        for (int off = 16; off > 0; off >>= 1) {
            denom += __shfl_xor_sync(0xffffffffu, denom, off);
            p0 += __shfl_xor_sync(0xffffffffu, p0, off);
            p1 += __shfl_xor_sync(0xffffffffu, p1, off);
            p2 += __shfl_xor_sync(0xffffffffu, p2, off);
            p3 += __shfl_xor_sync(0xffffffffu, p3, off);
            p4 += __shfl_xor_sync(0xffffffffu, p4, off);
            p5 += __shfl_xor_sync(0xffffffffu, p5, off);
            p6 += __shfl_xor_sync(0xffffffffu, p6, off);
            p7 += __shfl_xor_sync(0xffffffffu, p7, off);
        }
        if (lane == 0) {
            float c = sCent[h] / denom;
            float* dst = g_vc + rowbn*DD + h*8;
            dst[0]=p0*c; dst[1]=p1*c; dst[2]=p2*c; dst[3]=p3*c;
            dst[4]=p4*c; dst[5]=p5*c; dst[6]=p6*c; dst[7]=p7*c;
        }
    }

    __syncthreads();
    for (int t = tid; t < HH*NN; t += 256) {
        int h = t >> 9, j = t & 511;
        g_elog[(((size_t)b*HH + h)*NN + i)*NN + j] = sElog[h*520 + j];
    }
}

// ---------------------------------------------------------------------------
// K3: fused edge finish + MLP (unchanged from R11).
// ---------------------------------------------------------------------------
__global__ void __launch_bounds__(256, 1)
k_edge_finish_mlp(const float* __restrict__ e,
                  const float* __restrict__ WoE,
                  const float* __restrict__ lg1, const float* __restrict__ lb1,
                  const float* __restrict__ lg2, const float* __restrict__ lb2,
                  const float* __restrict__ W1, const float* __restrict__ b1,
                  const float* __restrict__ W2, const float* __restrict__ b2,
                  float* __restrict__ e_out)
{
    extern __shared__ float sm[];
    float*    sA   = sm + KA_OFF;
    uint32_t* sW1  = (uint32_t*)(sm + KW1_OFF);
    uint32_t* sH   = (uint32_t*)(sm + KH_OFF);
    uint32_t* sW2  = (uint32_t*)(sm + KW2_OFF);
    float*    sB1  = sm + KB1_OFF;
    float*    sB2  = sm + KB2_OFF;
    float*    sWoe = sm + KWOE_OFF;
    float*    sEl  = sm + KEL_OFF;
    float*    sG1  = sm + KG1_OFF;
    float*    sBe1 = sm + KBE1_OFF;
    float*    sG2  = sm + KG2_OFF;
    float*    sBe2 = sm + KBE2_OFF;

    const int tid  = threadIdx.x;
    const int lane = tid & 31;
    const int warp = tid >> 5;
    const int gid  = lane >> 2;
    const int tig  = lane & 3;

    const int bx = blockIdx.x;
    const int jc = bx & 3;
    const int i  = bx >> 2;
    const int b  = blockIdx.y;
    const int rowbn = b*NN + i;
    const size_t gj0 = (size_t)rowbn*NN + jc*128;

    for (int t = tid; t < 64*DHH; t += 256) {
        int k = t >> 7, u = t & 127;
        sW1[k*136 + u] = f2tf32(W1[t]);
    }
    for (int t = tid; t < DHH*64; t += 256) {
        int u = t >> 6, c = t & 63;
        sW2[u*72 + c] = f2tf32(W2[t]);
    }
    for (int t = tid; t < 512; t += 256) sWoe[t] = WoE[t];
    if (tid < 128) sB1[tid] = b1[tid];
    if (tid < 64) {
        sB2[tid]  = b2[tid];
        sG1[tid]  = lg1[tid]; sBe1[tid] = lb1[tid];
        sG2[tid]  = lg2[tid]; sBe2[tid] = lb2[tid];
    }
    for (int t = tid; t < 1024; t += 256) {
        int h = t >> 7, jl = t & 127;
        sEl[h*128 + jl] = g_elog[(((size_t)b*HH + h)*NN + i)*NN + jc*128 + jl];
    }
    for (int t = tid; t < 128*16; t += 256) {
        int row = t >> 4, q = t & 15;
        float4 v = *(const float4*)(e + (gj0 + row)*DD + q*4);
        *(float4*)(sA + row*68 + q*4) = v;
    }
    __syncthreads();

    // phase A: e3 = LN2( LN1(x) + El @ WoE ) in sA
    {
        const int r     = tid >> 1;
        const int halfc = tid & 1;
        const int c0    = halfc*32;

        float s = 0.f, sq = 0.f;
        #pragma unroll
        for (int c = 0; c < 32; c++) {
            float v = sA[r*68 + c0 + c];
            s += v; sq += v*v;
        }
        s  += __shfl_xor_sync(0xffffffffu, s, 1);
        sq += __shfl_xor_sync(0xffffffffu, sq, 1);
        float m = s*(1.f/64.f);
        float rstd = rsqrtf(sq*(1.f/64.f) - m*m + 1e-5f);

        float el0=sEl[r], el1=sEl[128+r], el2=sEl[256+r], el3=sEl[384+r];
        float el4=sEl[512+r], el5=sEl[640+r], el6=sEl[768+r], el7=sEl[896+r];

        float y[32];
        #pragma unroll
        for (int c = 0; c < 32; c++) {
            int k = c0 + c;
            float x = sA[r*68 + k];
            float a = (x - m)*rstd*sG1[k] + sBe1[k];
            a += el0*sWoe[k]       + el1*sWoe[64 + k]
               + el2*sWoe[128 + k] + el3*sWoe[192 + k]
               + el4*sWoe[256 + k] + el5*sWoe[320 + k]
               + el6*sWoe[384 + k] + el7*sWoe[448 + k];
            y[c] = a;
        }
        float s2 = 0.f, q2 = 0.f;
        #pragma unroll
        for (int c = 0; c < 32; c++) { s2 += y[c]; q2 += y[c]*y[c]; }
        s2 += __shfl_xor_sync(0xffffffffu, s2, 1);
        q2 += __shfl_xor_sync(0xffffffffu, q2, 1);
        float m2 = s2*(1.f/64.f);
        float rstd2 = rsqrtf(q2*(1.f/64.f) - m2*m2 + 1e-5f);
        #pragma unroll
        for (int c = 0; c < 32; c++) {
            int k = c0 + c;
            sA[r*68 + k] = (y[c] - m2)*rstd2*sG2[k] + sBe2[k];
        }
    }
    __syncthreads();

    // phase B: tf32 mma MLP
    const int row0 = warp*16 + gid;
    const int row1 = row0 + 8;

    uint32_t af0[8], af1[8], af2[8], af3[8];
    #pragma unroll
    for (int kt = 0; kt < 8; kt++) {
        int c0 = kt*8 + tig;
        af0[kt] = f2tf32(sA[row0*68 + c0]);
        af1[kt] = f2tf32(sA[row1*68 + c0]);
        af2[kt] = f2tf32(sA[row0*68 + c0 + 4]);
        af3[kt] = f2tf32(sA[row1*68 + c0 + 4]);
    }

    #pragma unroll
    for (int nc = 0; nc < 4; nc++) {
        float a00=0,a01=0,a02=0,a03=0;
        float a10=0,a11=0,a12=0,a13=0;
        float a20=0,a21=0,a22=0,a23=0;
        float a30=0,a31=0,a32=0,a33=0;
        #pragma unroll
        for (int kt = 0; kt < 8; kt++) {
            const uint32_t* w = sW1 + (kt*8 + tig)*136 + nc*32 + gid;
            uint32_t b00 = w[0],    b01 = w[4*136];
            uint32_t b10 = w[8],    b11 = w[4*136 + 8];
            uint32_t b20 = w[16],   b21 = w[4*136 + 16];
            uint32_t b30 = w[24],   b31 = w[4*136 + 24];
            mma_tf32(a00,a01,a02,a03, af0[kt],af1[kt],af2[kt],af3[kt], b00,b01);
            mma_tf32(a10,a11,a12,a13, af0[kt],af1[kt],af2[kt],af3[kt], b10,b11);
            mma_tf32(a20,a21,a22,a23, af0[kt],af1[kt],af2[kt],af3[kt], b20,b21);
            mma_tf32(a30,a31,a32,a33, af0[kt],af1[kt],af2[kt],af3[kt], b30,b31);
        }
        #pragma unroll
        for (int nt = 0; nt < 4; nt++) {
            float c0v, c1v, c2v, c3v;
            if (nt == 0)      { c0v=a00; c1v=a01; c2v=a02; c3v=a03; }
            else if (nt == 1) { c0v=a10; c1v=a11; c2v=a12; c3v=a13; }
            else if (nt == 2) { c0v=a20; c1v=a21; c2v=a22; c3v=a23; }
            else              { c0v=a30; c1v=a31; c2v=a32; c3v=a33; }
            int c = nc*32 + nt*8 + 2*tig;
            float bb0 = sB1[c], bb1 = sB1[c+1];
            sH[row0*132 + c    ] = f2tf32(fmaxf(c0v + bb0, 0.f));
            sH[row0*132 + c + 1] = f2tf32(fmaxf(c1v + bb1, 0.f));
            sH[row1*132 + c    ] = f2tf32(fmaxf(c2v + bb0, 0.f));
            sH[row1*132 + c + 1] = f2tf32(fmaxf(c3v + bb1, 0.f));
        }
    }
    __syncwarp();

    #pragma unroll
    for (int nc = 0; nc < 2; nc++) {
        float a00=0,a01=0,a02=0,a03=0;
        float a10=0,a11=0,a12=0,a13=0;
        float a20=0,a21=0,a22=0,a23=0;
        float a30=0,a31=0,a32=0,a33=0;
        #pragma unroll
        for (int kt = 0; kt < 16; kt++) {
            int c0 = kt*8 + tig;
            uint32_t h0 = sH[row0*132 + c0];
            uint32_t h1 = sH[row1*132 + c0];
            uint32_t h2 = sH[row0*132 + c0 + 4];
            uint32_t h3 = sH[row1*132 + c0 + 4];
            const uint32_t* w = sW2 + c0*72 + nc*32 + gid;
            uint32_t b00 = w[0],  b01 = w[4*72];
            uint32_t b10 = w[8],  b11 = w[4*72 + 8];
            uint32_t b20 = w[16], b21 = w[4*72 + 16];
            uint32_t b30 = w[24], b31 = w[4*72 + 24];
            mma_tf32(a00,a01,a02,a03, h0,h1,h2,h3, b00,b01);
            mma_tf32(a10,a11,a12,a13, h0,h1,h2,h3, b10,b11);
            mma_tf32(a20,a21,a22,a23, h0,h1,h2,h3, b20,b21);
            mma_tf32(a30,a31,a32,a33, h0,h1,h2,h3, b30,b31);
        }
        #pragma unroll
        for (int nt = 0; nt < 4; nt++) {
            float c0v, c1v, c2v, c3v;
            if (nt == 0)      { c0v=a00; c1v=a01; c2v=a02; c3v=a03; }
            else if (nt == 1) { c0v=a10; c1v=a11; c2v=a12; c3v=a13; }
            else if (nt == 2) { c0v=a20; c1v=a21; c2v=a22; c3v=a23; }
            else              { c0v=a30; c1v=a31; c2v=a32; c3v=a33; }
            int c = nc*32 + nt*8 + 2*tig;
            float b20v = sB2[c], b21v = sB2[c+1];
            float r00 = sA[row0*68 + c    ] + fmaxf(c0v + b20v, 0.f);
            float r01 = sA[row0*68 + c + 1] + fmaxf(c1v + b21v, 0.f);
            float r10 = sA[row1*68 + c    ] + fmaxf(c2v + b20v, 0.f);
            float r11 = sA[row1*68 + c + 1] + fmaxf(c3v + b21v, 0.f);
            *(float2*)(e_out + (gj0 + row0)*DD + c) = make_float2(r00, r01);
            *(float2*)(e_out + (gj0 + row1)*DD + c) = make_float2(r10, r11);
        }
    }
}

// ---------------------------------------------------------------------------
// K4: node finish.
// ---------------------------------------------------------------------------
__global__ void k_node_finish(const float* __restrict__ Wo_n,
                              const float* __restrict__ lng,
                              const float* __restrict__ lnb,
                              const float* __restrict__ W1,
                              const float* __restrict__ Bi1,
                              const float* __restrict__ W2,
                              const float* __restrict__ Bi2,
                              float* __restrict__ n_out)
{
    int row = blockIdx.x;
    int o = threadIdx.x;
    __shared__ float svc[DD];
    __shared__ float sn2[DD];
    __shared__ float sn3[DD];
    __shared__ float sh[DHH];
    svc[o] = g_vc[row*DD + o];
    __syncthreads();
    float acc = 0.f;
    #pragma unroll
    for (int k = 0; k < DD; k++) acc += svc[k]*Wo_n[k*DD + o];
    float n2 = g_n1[row*DD + o] + acc;
    sn2[o] = n2;
    __syncthreads();
    float s = 0.f;
    #pragma unroll
    for (int k = 0; k < DD; k++) s += sn2[k];
    float m = s*(1.f/DD);
    float v = 0.f;
    #pragma unroll
    for (int k = 0; k < DD; k++) { float d = sn2[k]-m; v += d*d; }
    v *= (1.f/DD);
    float rstd = rsqrtf(v + 1e-5f);
    float n3 = (n2-m)*rstd*lng[o] + lnb[o];
    sn3[o] = n3;
    __syncthreads();
    #pragma unroll
    for (int uu = 0; uu < 2; uu++) {
        int u = o + uu*64;
        float h = Bi1[u];
        #pragma unroll
        for (int k = 0; k < DD; k++) h += sn3[k]*W1[k*DHH + u];
        sh[u] = fmaxf(h, 0.f);
    }
    __syncthreads();
    float oacc = Bi2[o];
    #pragma unroll
    for (int u = 0; u < DHH; u++) oacc += sh[u]*W2[u*DD + o];
    n_out[row*DD + o] = n3 + fmaxf(oacc, 0.f);
}

extern "C" void kernel_launch(void* const* d_in, const int* in_sizes, int n_in,
                              void* d_out, int out_size)
{
    const float* n       = (const float*)d_in[0];
    const float* e       = (const float*)d_in[1];
    const float* Wq      = (const float*)d_in[2];
    const float* Wk      = (const float*)d_in[3];
    const float* Wv      = (const float*)d_in[4];
    const float* Wo_n    = (const float*)d_in[5];
    const float* We      = (const float*)d_in[6];
    const float* Wg      = (const float*)d_in[7];
    const float* Wo_e    = (const float*)d_in[8];
    const float* ln_n1_g = (const float*)d_in[9];
    const float* ln_n1_b = (const float*)d_in[10];
    const float* ln_e1_g = (const float*)d_in[11];
    const float* ln_e1_b = (const float*)d_in[12];
    const float* ln_n2_g = (const float*)d_in[13];
    const float* ln_n2_b = (const float*)d_in[14];
    const float* ln_e2_g = (const float*)d_in[15];
    const float* ln_e2_b = (const float*)d_in[16];
    const float* mn_w1   = (const float*)d_in[17];
    const float* mn_b1   = (const float*)d_in[18];
    const float* mn_w2   = (const float*)d_in[19];
    const float* mn_b2   = (const float*)d_in[20];
    const float* me_w1   = (const float*)d_in[21];
    const float* me_b1   = (const float*)d_in[22];
    const float* me_w2   = (const float*)d_in[23];
    const float* me_b2   = (const float*)d_in[24];

    float* out   = (float*)d_out;
    float* n_out = out;
    float* e_out = out + BB*NN*DD;

    cudaFuncSetAttribute(k_edge, cudaFuncAttributeMaxDynamicSharedMemorySize, EDGE_SMEM_BYTES);
    cudaFuncSetAttribute(k_edge_finish_mlp, cudaFuncAttributeMaxDynamicSharedMemorySize, K3_SMEM_BYTES);

    k_node_prep<<<BB*NN, 64>>>(n, Wq, Wk, Wv, ln_n1_g, ln_n1_b);

    dim3 grid2(NN, BB);
    k_edge<<<grid2, 256, EDGE_SMEM_BYTES>>>(e, We, Wg, ln_e1_g, ln_e1_b);

    dim3 grid3(4*NN, BB);
    k_edge_finish_mlp<<<grid3, 256, K3_SMEM_BYTES>>>(e, Wo_e,
                                                     ln_e1_g, ln_e1_b,
                                                     ln_e2_g, ln_e2_b,
                                                     me_w1, me_b1, me_w2, me_b2,
                                                     e_out);

    k_node_finish<<<BB*NN, 64>>>(Wo_n, ln_n2_g, ln_n2_b,
                                 mn_w1, mn_b1, mn_w2, mn_b2, n_out);
}